// round 1
// baseline (speedup 1.0000x reference)
#include <cuda_runtime.h>
#include <math.h>

#define MAXN 50000
#define HD 128
#define NHEAD 8

__device__ float g_Q[(size_t)MAXN * HD];
__device__ float g_K[(size_t)MAXN * HD];
__device__ float g_V[(size_t)MAXN * HD];
__device__ float g_z[(size_t)MAXN * NHEAD];

// ---------------------------------------------------------------------------
// QKV projection: out[n, c] = sum_k h[n,k] * W[k,c] + b[c]
// grid.x tiles 64 rows, grid.y in {0,1,2} selects Q/K/V.
// smem: h tile 64x128 (stride 132 to avoid bank conflicts) + full W 128x128.
// Each thread computes a 4-row x 8-col register tile.
// ---------------------------------------------------------------------------
extern __shared__ float smem[];

__global__ __launch_bounds__(256) void qkv_kernel(
    const float* __restrict__ h,
    const float* __restrict__ Wq, const float* __restrict__ bq,
    const float* __restrict__ Wk, const float* __restrict__ bk,
    const float* __restrict__ Wv, const float* __restrict__ bv,
    int N)
{
    const float* W;
    const float* b;
    float* out;
    if (blockIdx.y == 0)      { W = Wq; b = bq; out = g_Q; }
    else if (blockIdx.y == 1) { W = Wk; b = bk; out = g_K; }
    else                      { W = Wv; b = bv; out = g_V; }

    float* sh_h = smem;               // 64 rows x stride 132
    float* sh_w = smem + 64 * 132;    // 128 x 128

    const int tid  = threadIdx.x;
    const int row0 = blockIdx.x * 64;

    // Load h tile (64 x 128 floats = 2048 float4)
    #pragma unroll
    for (int i = 0; i < 8; i++) {
        int idx4 = tid + i * 256;          // 0..2047
        int r    = idx4 >> 5;              // row in tile
        int c4   = idx4 & 31;              // float4 col
        float4 v = make_float4(0.f, 0.f, 0.f, 0.f);
        int gr = row0 + r;
        if (gr < N) v = *(const float4*)&h[(size_t)gr * HD + c4 * 4];
        *(float4*)&sh_h[r * 132 + c4 * 4] = v;
    }
    // Load W (128 x 128 = 4096 float4)
    #pragma unroll
    for (int i = 0; i < 16; i++) {
        int idx4 = tid + i * 256;
        *(float4*)&sh_w[idx4 * 4] = *(const float4*)&W[idx4 * 4];
    }
    __syncthreads();

    const int rg = tid >> 4;   // 0..15 -> rows rg*4 .. rg*4+3
    const int cg = tid & 15;   // 0..15 -> cols cg*8 .. cg*8+7

    float acc[4][8];
    #pragma unroll
    for (int i = 0; i < 4; i++)
        #pragma unroll
        for (int j = 0; j < 8; j++) acc[i][j] = 0.f;

    #pragma unroll 4
    for (int k = 0; k < 128; k++) {
        float4 w0 = *(float4*)&sh_w[k * 128 + cg * 8];
        float4 w1 = *(float4*)&sh_w[k * 128 + cg * 8 + 4];
        #pragma unroll
        for (int i = 0; i < 4; i++) {
            float a = sh_h[(rg * 4 + i) * 132 + k];
            acc[i][0] += a * w0.x;
            acc[i][1] += a * w0.y;
            acc[i][2] += a * w0.z;
            acc[i][3] += a * w0.w;
            acc[i][4] += a * w1.x;
            acc[i][5] += a * w1.y;
            acc[i][6] += a * w1.z;
            acc[i][7] += a * w1.w;
        }
    }

    float bb[8];
    #pragma unroll
    for (int j = 0; j < 8; j++) bb[j] = __ldg(&b[cg * 8 + j]);

    #pragma unroll
    for (int i = 0; i < 4; i++) {
        int gr = row0 + rg * 4 + i;
        if (gr < N) {
            float4 o0 = make_float4(acc[i][0] + bb[0], acc[i][1] + bb[1],
                                    acc[i][2] + bb[2], acc[i][3] + bb[3]);
            float4 o1 = make_float4(acc[i][4] + bb[4], acc[i][5] + bb[5],
                                    acc[i][6] + bb[6], acc[i][7] + bb[7]);
            *(float4*)&out[(size_t)gr * HD + cg * 8]     = o0;
            *(float4*)&out[(size_t)gr * HD + cg * 8 + 4] = o1;
        }
    }
}

// ---------------------------------------------------------------------------
// Edge kernel: one warp per edge. lane covers 4 consecutive channels,
// head = lane>>2. Coalesced 512B gathers of K[src], Q[dst], V[src];
// one contiguous red.global.v4.f32 per warp for wV; 8 z-atomics per warp.
// ---------------------------------------------------------------------------
__global__ __launch_bounds__(256) void edge_kernel(
    const int* __restrict__ src, const int* __restrict__ dst,
    const float* __restrict__ dis,
    const float* __restrict__ att_w, const float* __restrict__ att_b,
    float* __restrict__ out_wV, int E)
{
    int e = (blockIdx.x * blockDim.x + threadIdx.x) >> 5;
    int lane = threadIdx.x & 31;
    if (e >= E) return;

    int s = __ldg(&src[e]);
    int d = __ldg(&dst[e]);

    float4 kv = *(const float4*)&g_K[(size_t)s * HD + lane * 4];
    float4 qv = *(const float4*)&g_Q[(size_t)d * HD + lane * 4];

    float dot = kv.x * qv.x + kv.y * qv.y + kv.z * qv.z + kv.w * qv.w;
    dot += __shfl_xor_sync(0xffffffffu, dot, 1);
    dot += __shfl_xor_sync(0xffffffffu, dot, 2);

    int head = lane >> 2;
    float bias = __ldg(&dis[d]) * __ldg(&att_w[head]) + __ldg(&att_b[head]);
    float sc = (dot + bias) * 0.25f;            // / SCALE, SCALE = sqrt(16) = 4
    sc = fminf(fmaxf(sc, -5.f), 5.f);
    sc = expf(sc);

    float4 vv = *(const float4*)&g_V[(size_t)s * HD + lane * 4];
    float* p = &out_wV[(size_t)d * HD + lane * 4];
    asm volatile("red.global.add.v4.f32 [%0], {%1, %2, %3, %4};"
                 :: "l"(p), "f"(vv.x * sc), "f"(vv.y * sc),
                    "f"(vv.z * sc), "f"(vv.w * sc)
                 : "memory");

    if ((lane & 3) == 0)
        atomicAdd(&g_z[(size_t)d * NHEAD + head], sc);
}

// ---------------------------------------------------------------------------
// Finalize: out = wV / z  (in place on d_out)
// ---------------------------------------------------------------------------
__global__ __launch_bounds__(256) void finalize_kernel(float* __restrict__ out, int N)
{
    int i = blockIdx.x * blockDim.x + threadIdx.x;   // one float4 per thread
    if (i >= N * 32) return;
    int n    = i >> 5;
    int q    = i & 31;       // float4 index in row
    int head = q >> 2;
    float inv = 1.0f / g_z[(size_t)n * NHEAD + head];
    float4 v = *(float4*)&out[(size_t)n * HD + q * 4];
    v.x *= inv; v.y *= inv; v.z *= inv; v.w *= inv;
    *(float4*)&out[(size_t)n * HD + q * 4] = v;
}

// ---------------------------------------------------------------------------
extern "C" void kernel_launch(void* const* d_in, const int* in_sizes, int n_in,
                              void* d_out, int out_size)
{
    const float* h     = (const float*)d_in[0];
    const float* dis   = (const float*)d_in[1];
    const float* Wq    = (const float*)d_in[2];
    const float* bq    = (const float*)d_in[3];
    const float* Wk    = (const float*)d_in[4];
    const float* bk    = (const float*)d_in[5];
    const float* Wv    = (const float*)d_in[6];
    const float* bv    = (const float*)d_in[7];
    const float* att_w = (const float*)d_in[8];
    const float* att_b = (const float*)d_in[9];
    const int*   src   = (const int*)d_in[10];
    const int*   dst   = (const int*)d_in[11];

    int N = in_sizes[1];     // dis has N elements
    int E = in_sizes[10];    // src has E elements
    float* out = (float*)d_out;

    // Zero accumulators (d_out holds wV; g_z holds softmax denominators)
    cudaMemsetAsync(out, 0, (size_t)out_size * sizeof(float));
    void* zptr = nullptr;
    cudaGetSymbolAddress(&zptr, g_z);
    cudaMemsetAsync(zptr, 0, (size_t)N * NHEAD * sizeof(float));

    // QKV projections
    size_t smem_bytes = (64 * 132 + 128 * 128) * sizeof(float);   // ~97 KB
    cudaFuncSetAttribute(qkv_kernel, cudaFuncAttributeMaxDynamicSharedMemorySize,
                         (int)smem_bytes);
    dim3 qkv_grid((N + 63) / 64, 3);
    qkv_kernel<<<qkv_grid, 256, smem_bytes>>>(h, Wq, bq, Wk, bk, Wv, bv, N);

    // Edge scatter (8 warps per block -> 8 edges per block)
    edge_kernel<<<(E + 7) / 8, 256>>>(src, dst, dis, att_w, att_b, out, E);

    // Divide by z
    finalize_kernel<<<((size_t)N * 32 + 255) / 256, 256>>>(out, N);
}

// round 2
// speedup vs baseline: 1.4690x; 1.4690x over previous
#include <cuda_runtime.h>
#include <cuda_bf16.h>
#include <math.h>

#define MAXN 50000
#define HD 128
#define NHEAD 8
#define TS 136   // smem tile stride in bf16 elements (272B rows: conflict-free ldmatrix)

__device__ float g_Q[(size_t)MAXN * HD];
__device__ float g_K[(size_t)MAXN * HD];
__device__ float g_V[(size_t)MAXN * HD];
__device__ float g_z[(size_t)MAXN * NHEAD];

// ---------------------------------------------------------------------------
// QKV projection via bf16 tensor cores with 2-term split (3-pass compensation).
// out[n,c] = sum_k h[n,k]*W[k,c] + b[c],  per grid.y in {Q,K,V}.
// Block: 128 rows x 128 cols, K=128 in one shot. 8 warps in 4x2 layout,
// each warp: 32(M) x 64(N) via 2x8 mma.m16n8k16 tiles.
// ---------------------------------------------------------------------------
extern __shared__ unsigned short smem_bf[];

__global__ __launch_bounds__(256) void qkv_mma_kernel(
    const float* __restrict__ h,
    const float* __restrict__ Wq, const float* __restrict__ bq,
    const float* __restrict__ Wk, const float* __restrict__ bk,
    const float* __restrict__ Wv, const float* __restrict__ bv,
    int N)
{
    const float* W;
    const float* b;
    float* out;
    if (blockIdx.y == 0)      { W = Wq; b = bq; out = g_Q; }
    else if (blockIdx.y == 1) { W = Wk; b = bk; out = g_K; }
    else                      { W = Wv; b = bv; out = g_V; }

    unsigned short* A_hi = smem_bf;
    unsigned short* A_lo = A_hi + 128 * TS;
    unsigned short* B_hi = A_lo + 128 * TS;
    unsigned short* B_lo = B_hi + 128 * TS;

    const int tid  = threadIdx.x;
    const int row0 = blockIdx.x * 128;

    // ---- Load h tile (128x128 fp32) -> split to bf16 hi/lo in smem ----
    #pragma unroll
    for (int i = 0; i < 16; i++) {
        int idx = tid + i * 256;          // 0..4095 float4 slots
        int r   = idx >> 5;
        int c4  = idx & 31;
        float4 v = make_float4(0.f, 0.f, 0.f, 0.f);
        int gr = row0 + r;
        if (gr < N) v = *(const float4*)&h[(size_t)gr * HD + c4 * 4];
        float vv[4] = {v.x, v.y, v.z, v.w};
        unsigned short hs[4], ls[4];
        #pragma unroll
        for (int j = 0; j < 4; j++) {
            __nv_bfloat16 hb = __float2bfloat16(vv[j]);
            float lf = vv[j] - __bfloat162float(hb);
            __nv_bfloat16 lb = __float2bfloat16(lf);
            hs[j] = __bfloat16_as_ushort(hb);
            ls[j] = __bfloat16_as_ushort(lb);
        }
        uint2 ph, pl;
        ph.x = (unsigned)hs[0] | ((unsigned)hs[1] << 16);
        ph.y = (unsigned)hs[2] | ((unsigned)hs[3] << 16);
        pl.x = (unsigned)ls[0] | ((unsigned)ls[1] << 16);
        pl.y = (unsigned)ls[2] | ((unsigned)ls[3] << 16);
        *(uint2*)&A_hi[r * TS + c4 * 4] = ph;
        *(uint2*)&A_lo[r * TS + c4 * 4] = pl;
    }
    // ---- Load W (128x128 fp32, k-major rows) -> bf16 hi/lo ----
    #pragma unroll
    for (int i = 0; i < 16; i++) {
        int idx = tid + i * 256;
        int r   = idx >> 5;
        int c4  = idx & 31;
        float4 v = *(const float4*)&W[(size_t)r * HD + c4 * 4];
        float vv[4] = {v.x, v.y, v.z, v.w};
        unsigned short hs[4], ls[4];
        #pragma unroll
        for (int j = 0; j < 4; j++) {
            __nv_bfloat16 hb = __float2bfloat16(vv[j]);
            float lf = vv[j] - __bfloat162float(hb);
            __nv_bfloat16 lb = __float2bfloat16(lf);
            hs[j] = __bfloat16_as_ushort(hb);
            ls[j] = __bfloat16_as_ushort(lb);
        }
        uint2 ph, pl;
        ph.x = (unsigned)hs[0] | ((unsigned)hs[1] << 16);
        ph.y = (unsigned)hs[2] | ((unsigned)hs[3] << 16);
        pl.x = (unsigned)ls[0] | ((unsigned)ls[1] << 16);
        pl.y = (unsigned)ls[2] | ((unsigned)ls[3] << 16);
        *(uint2*)&B_hi[r * TS + c4 * 4] = ph;
        *(uint2*)&B_lo[r * TS + c4 * 4] = pl;
    }
    __syncthreads();

    const int warp = tid >> 5;
    const int lane = tid & 31;
    const int wm = warp >> 1;          // 0..3
    const int wn = warp & 1;           // 0..1
    const int m_base = wm * 32;
    const int n_base = wn * 64;

    float acc[2][8][4];
    #pragma unroll
    for (int mt = 0; mt < 2; mt++)
        #pragma unroll
        for (int nt = 0; nt < 8; nt++)
            #pragma unroll
            for (int q = 0; q < 4; q++) acc[mt][nt][q] = 0.f;

    // ldmatrix address components
    const int a_row  = m_base + (lane & 15);
    const int a_coff = (lane >> 4) * 8;
    const int b_roff = (lane & 7) + ((lane >> 3) & 1) * 8;
    const int b_col  = n_base + (lane >> 4) * 8;

    const unsigned short* Aops[3] = {A_hi, A_hi, A_lo};
    const unsigned short* Bops[3] = {B_hi, B_lo, B_hi};

    for (int pass = 0; pass < 3; pass++) {
        const unsigned short* Ap = Aops[pass];
        const unsigned short* Bp = Bops[pass];
        #pragma unroll
        for (int ks = 0; ks < 8; ks++) {
            const int k0 = ks * 16;
            unsigned a[2][4];
            #pragma unroll
            for (int mt = 0; mt < 2; mt++) {
                unsigned addr = (unsigned)__cvta_generic_to_shared(
                    &Ap[(a_row + mt * 16) * TS + k0 + a_coff]);
                asm volatile(
                    "ldmatrix.sync.aligned.m8n8.x4.shared.b16 {%0,%1,%2,%3}, [%4];"
                    : "=r"(a[mt][0]), "=r"(a[mt][1]), "=r"(a[mt][2]), "=r"(a[mt][3])
                    : "r"(addr));
            }
            unsigned bf[8][2];
            #pragma unroll
            for (int np = 0; np < 4; np++) {
                unsigned addr = (unsigned)__cvta_generic_to_shared(
                    &Bp[(k0 + b_roff) * TS + b_col + np * 16]);
                unsigned r0, r1, r2, r3;
                asm volatile(
                    "ldmatrix.sync.aligned.m8n8.x4.trans.shared.b16 {%0,%1,%2,%3}, [%4];"
                    : "=r"(r0), "=r"(r1), "=r"(r2), "=r"(r3)
                    : "r"(addr));
                bf[np * 2][0] = r0; bf[np * 2][1] = r1;
                bf[np * 2 + 1][0] = r2; bf[np * 2 + 1][1] = r3;
            }
            #pragma unroll
            for (int mt = 0; mt < 2; mt++)
                #pragma unroll
                for (int nt = 0; nt < 8; nt++) {
                    asm volatile(
                        "mma.sync.aligned.m16n8k16.row.col.f32.bf16.bf16.f32 "
                        "{%0,%1,%2,%3}, {%4,%5,%6,%7}, {%8,%9}, {%0,%1,%2,%3};"
                        : "+f"(acc[mt][nt][0]), "+f"(acc[mt][nt][1]),
                          "+f"(acc[mt][nt][2]), "+f"(acc[mt][nt][3])
                        : "r"(a[mt][0]), "r"(a[mt][1]), "r"(a[mt][2]), "r"(a[mt][3]),
                          "r"(bf[nt][0]), "r"(bf[nt][1]));
                }
        }
    }

    // ---- Epilogue: add bias, store fp32 ----
    const int g  = lane >> 2;
    const int t2 = (lane & 3) * 2;
    #pragma unroll
    for (int mt = 0; mt < 2; mt++) {
        #pragma unroll
        for (int half = 0; half < 2; half++) {
            int r = row0 + m_base + mt * 16 + g + half * 8;
            if (r < N) {
                #pragma unroll
                for (int nt = 0; nt < 8; nt++) {
                    int col = n_base + nt * 8 + t2;
                    float2 o;
                    o.x = acc[mt][nt][half * 2 + 0] + __ldg(&b[col]);
                    o.y = acc[mt][nt][half * 2 + 1] + __ldg(&b[col + 1]);
                    *(float2*)&out[(size_t)r * HD + col] = o;
                }
            }
        }
    }
}

// ---------------------------------------------------------------------------
// Edge kernel: one warp per edge (unchanged from R1 — L2-bound, next target).
// ---------------------------------------------------------------------------
__global__ __launch_bounds__(256) void edge_kernel(
    const int* __restrict__ src, const int* __restrict__ dst,
    const float* __restrict__ dis,
    const float* __restrict__ att_w, const float* __restrict__ att_b,
    float* __restrict__ out_wV, int E)
{
    int e = (blockIdx.x * blockDim.x + threadIdx.x) >> 5;
    int lane = threadIdx.x & 31;
    if (e >= E) return;

    int s = __ldg(&src[e]);
    int d = __ldg(&dst[e]);

    float4 kv = *(const float4*)&g_K[(size_t)s * HD + lane * 4];
    float4 qv = *(const float4*)&g_Q[(size_t)d * HD + lane * 4];

    float dot = kv.x * qv.x + kv.y * qv.y + kv.z * qv.z + kv.w * qv.w;
    dot += __shfl_xor_sync(0xffffffffu, dot, 1);
    dot += __shfl_xor_sync(0xffffffffu, dot, 2);

    int head = lane >> 2;
    float bias = __ldg(&dis[d]) * __ldg(&att_w[head]) + __ldg(&att_b[head]);
    float sc = (dot + bias) * 0.25f;            // / SCALE, SCALE = sqrt(16) = 4
    sc = fminf(fmaxf(sc, -5.f), 5.f);
    sc = expf(sc);

    float4 vv = *(const float4*)&g_V[(size_t)s * HD + lane * 4];
    float* p = &out_wV[(size_t)d * HD + lane * 4];
    asm volatile("red.global.add.v4.f32 [%0], {%1, %2, %3, %4};"
                 :: "l"(p), "f"(vv.x * sc), "f"(vv.y * sc),
                    "f"(vv.z * sc), "f"(vv.w * sc)
                 : "memory");

    if ((lane & 3) == 0)
        atomicAdd(&g_z[(size_t)d * NHEAD + head], sc);
}

// ---------------------------------------------------------------------------
__global__ __launch_bounds__(256) void finalize_kernel(float* __restrict__ out, int N)
{
    int i = blockIdx.x * blockDim.x + threadIdx.x;
    if (i >= N * 32) return;
    int n    = i >> 5;
    int q    = i & 31;
    int head = q >> 2;
    float inv = 1.0f / g_z[(size_t)n * NHEAD + head];
    float4 v = *(float4*)&out[(size_t)n * HD + q * 4];
    v.x *= inv; v.y *= inv; v.z *= inv; v.w *= inv;
    *(float4*)&out[(size_t)n * HD + q * 4] = v;
}

// ---------------------------------------------------------------------------
extern "C" void kernel_launch(void* const* d_in, const int* in_sizes, int n_in,
                              void* d_out, int out_size)
{
    const float* h     = (const float*)d_in[0];
    const float* dis   = (const float*)d_in[1];
    const float* Wq    = (const float*)d_in[2];
    const float* bq    = (const float*)d_in[3];
    const float* Wk    = (const float*)d_in[4];
    const float* bk    = (const float*)d_in[5];
    const float* Wv    = (const float*)d_in[6];
    const float* bv    = (const float*)d_in[7];
    const float* att_w = (const float*)d_in[8];
    const float* att_b = (const float*)d_in[9];
    const int*   src   = (const int*)d_in[10];
    const int*   dst   = (const int*)d_in[11];

    int N = in_sizes[1];
    int E = in_sizes[10];
    float* out = (float*)d_out;

    cudaMemsetAsync(out, 0, (size_t)out_size * sizeof(float));
    void* zptr = nullptr;
    cudaGetSymbolAddress(&zptr, g_z);
    cudaMemsetAsync(zptr, 0, (size_t)N * NHEAD * sizeof(float));

    size_t smem_bytes = (size_t)4 * 128 * TS * sizeof(unsigned short);  // ~136 KB
    static bool attr_set = false;
    if (!attr_set) {
        cudaFuncSetAttribute(qkv_mma_kernel,
                             cudaFuncAttributeMaxDynamicSharedMemorySize,
                             (int)smem_bytes);
        attr_set = true;
    }
    dim3 qkv_grid((N + 127) / 128, 3);
    qkv_mma_kernel<<<qkv_grid, 256, smem_bytes>>>(h, Wq, bq, Wk, bk, Wv, bv, N);

    edge_kernel<<<(E + 7) / 8, 256>>>(src, dst, dis, att_w, att_b, out, E);

    finalize_kernel<<<((size_t)N * 32 + 255) / 256, 256>>>(out, N);
}

// round 3
// speedup vs baseline: 1.9826x; 1.3496x over previous
#include <cuda_runtime.h>
#include <cuda_bf16.h>
#include <math.h>

#define MAXN 50000
#define MAXE 800000
#define HD 128
#define NHEAD 8
#define TS 136   // smem tile stride in bf16 elements (272B rows: conflict-free ldmatrix)

__device__ float g_Q[(size_t)MAXN * HD];
__device__ float g_K[(size_t)MAXN * HD];
__device__ float g_V[(size_t)MAXN * HD];
__device__ int   g_count[MAXN];
__device__ int   g_start[MAXN];
__device__ int   g_cursor[MAXN];
__device__ int   g_csr_src[MAXE];
__device__ int   g_bsums[64];

// ---------------------------------------------------------------------------
// QKV projection via bf16 tensor cores, fused 2-term split:
// acc += Ahi*Bhi + Ahi*Blo + Alo*Bhi in a single k-loop (ldmatrix issued once).
// Block tile: 64 rows x 128 cols, K=128. smem ~104KB -> 2 CTAs/SM.
// 8 warps: wm = warp&3 (m16 tile), wn = warp>>2 (n64 half); warp = 16x64.
// ---------------------------------------------------------------------------
extern __shared__ unsigned short smem_bf[];

__global__ __launch_bounds__(256, 2) void qkv_mma_kernel(
    const float* __restrict__ h,
    const float* __restrict__ Wq, const float* __restrict__ bq,
    const float* __restrict__ Wk, const float* __restrict__ bk,
    const float* __restrict__ Wv, const float* __restrict__ bv,
    int N)
{
    const float* W;
    const float* b;
    float* out;
    if (blockIdx.y == 0)      { W = Wq; b = bq; out = g_Q; }
    else if (blockIdx.y == 1) { W = Wk; b = bk; out = g_K; }
    else                      { W = Wv; b = bv; out = g_V; }

    unsigned short* A_hi = smem_bf;                 // 64 x TS
    unsigned short* A_lo = A_hi + 64 * TS;          // 64 x TS
    unsigned short* B_hi = A_lo + 64 * TS;          // 128 x TS
    unsigned short* B_lo = B_hi + 128 * TS;         // 128 x TS

    const int tid  = threadIdx.x;
    const int row0 = blockIdx.x * 64;

    // ---- Load h tile (64x128 fp32) -> split to bf16 hi/lo ----
    #pragma unroll
    for (int i = 0; i < 8; i++) {
        int idx = tid + i * 256;          // 0..2047 float4 slots
        int r   = idx >> 5;
        int c4  = idx & 31;
        float4 v = make_float4(0.f, 0.f, 0.f, 0.f);
        int gr = row0 + r;
        if (gr < N) v = *(const float4*)&h[(size_t)gr * HD + c4 * 4];
        float vv[4] = {v.x, v.y, v.z, v.w};
        unsigned short hs[4], ls[4];
        #pragma unroll
        for (int j = 0; j < 4; j++) {
            __nv_bfloat16 hb = __float2bfloat16(vv[j]);
            float lf = vv[j] - __bfloat162float(hb);
            __nv_bfloat16 lb = __float2bfloat16(lf);
            hs[j] = __bfloat16_as_ushort(hb);
            ls[j] = __bfloat16_as_ushort(lb);
        }
        uint2 ph, pl;
        ph.x = (unsigned)hs[0] | ((unsigned)hs[1] << 16);
        ph.y = (unsigned)hs[2] | ((unsigned)hs[3] << 16);
        pl.x = (unsigned)ls[0] | ((unsigned)ls[1] << 16);
        pl.y = (unsigned)ls[2] | ((unsigned)ls[3] << 16);
        *(uint2*)&A_hi[r * TS + c4 * 4] = ph;
        *(uint2*)&A_lo[r * TS + c4 * 4] = pl;
    }
    // ---- Load W (128x128 fp32) -> bf16 hi/lo ----
    #pragma unroll
    for (int i = 0; i < 16; i++) {
        int idx = tid + i * 256;
        int r   = idx >> 5;
        int c4  = idx & 31;
        float4 v = *(const float4*)&W[(size_t)r * HD + c4 * 4];
        float vv[4] = {v.x, v.y, v.z, v.w};
        unsigned short hs[4], ls[4];
        #pragma unroll
        for (int j = 0; j < 4; j++) {
            __nv_bfloat16 hb = __float2bfloat16(vv[j]);
            float lf = vv[j] - __bfloat162float(hb);
            __nv_bfloat16 lb = __float2bfloat16(lf);
            hs[j] = __bfloat16_as_ushort(hb);
            ls[j] = __bfloat16_as_ushort(lb);
        }
        uint2 ph, pl;
        ph.x = (unsigned)hs[0] | ((unsigned)hs[1] << 16);
        ph.y = (unsigned)hs[2] | ((unsigned)hs[3] << 16);
        pl.x = (unsigned)ls[0] | ((unsigned)ls[1] << 16);
        pl.y = (unsigned)ls[2] | ((unsigned)ls[3] << 16);
        *(uint2*)&B_hi[r * TS + c4 * 4] = ph;
        *(uint2*)&B_lo[r * TS + c4 * 4] = pl;
    }
    __syncthreads();

    const int warp = tid >> 5;
    const int lane = tid & 31;
    const int wm = warp & 3;           // m16 tile index
    const int wn = warp >> 2;          // n64 half
    const int m_base = wm * 16;
    const int n_base = wn * 64;

    float acc[8][4];
    #pragma unroll
    for (int nt = 0; nt < 8; nt++)
        #pragma unroll
        for (int q = 0; q < 4; q++) acc[nt][q] = 0.f;

    const int a_row  = m_base + (lane & 15);
    const int a_coff = (lane >> 4) * 8;
    const int b_roff = (lane & 7) + ((lane >> 3) & 1) * 8;
    const int b_col  = n_base + (lane >> 4) * 8;

    #pragma unroll
    for (int ks = 0; ks < 8; ks++) {
        const int k0 = ks * 16;
        unsigned ah[4], al[4];
        {
            unsigned addr = (unsigned)__cvta_generic_to_shared(
                &A_hi[a_row * TS + k0 + a_coff]);
            asm volatile(
                "ldmatrix.sync.aligned.m8n8.x4.shared.b16 {%0,%1,%2,%3}, [%4];"
                : "=r"(ah[0]), "=r"(ah[1]), "=r"(ah[2]), "=r"(ah[3]) : "r"(addr));
            addr = (unsigned)__cvta_generic_to_shared(
                &A_lo[a_row * TS + k0 + a_coff]);
            asm volatile(
                "ldmatrix.sync.aligned.m8n8.x4.shared.b16 {%0,%1,%2,%3}, [%4];"
                : "=r"(al[0]), "=r"(al[1]), "=r"(al[2]), "=r"(al[3]) : "r"(addr));
        }
        unsigned bh[8][2], bl[8][2];
        #pragma unroll
        for (int np = 0; np < 4; np++) {
            unsigned addr = (unsigned)__cvta_generic_to_shared(
                &B_hi[(k0 + b_roff) * TS + b_col + np * 16]);
            unsigned r0, r1, r2, r3;
            asm volatile(
                "ldmatrix.sync.aligned.m8n8.x4.trans.shared.b16 {%0,%1,%2,%3}, [%4];"
                : "=r"(r0), "=r"(r1), "=r"(r2), "=r"(r3) : "r"(addr));
            bh[np * 2][0] = r0; bh[np * 2][1] = r1;
            bh[np * 2 + 1][0] = r2; bh[np * 2 + 1][1] = r3;
            addr = (unsigned)__cvta_generic_to_shared(
                &B_lo[(k0 + b_roff) * TS + b_col + np * 16]);
            asm volatile(
                "ldmatrix.sync.aligned.m8n8.x4.trans.shared.b16 {%0,%1,%2,%3}, [%4];"
                : "=r"(r0), "=r"(r1), "=r"(r2), "=r"(r3) : "r"(addr));
            bl[np * 2][0] = r0; bl[np * 2][1] = r1;
            bl[np * 2 + 1][0] = r2; bl[np * 2 + 1][1] = r3;
        }
        #pragma unroll
        for (int nt = 0; nt < 8; nt++) {
            asm volatile(
                "mma.sync.aligned.m16n8k16.row.col.f32.bf16.bf16.f32 "
                "{%0,%1,%2,%3}, {%4,%5,%6,%7}, {%8,%9}, {%0,%1,%2,%3};"
                : "+f"(acc[nt][0]), "+f"(acc[nt][1]), "+f"(acc[nt][2]), "+f"(acc[nt][3])
                : "r"(ah[0]), "r"(ah[1]), "r"(ah[2]), "r"(ah[3]),
                  "r"(bh[nt][0]), "r"(bh[nt][1]));
            asm volatile(
                "mma.sync.aligned.m16n8k16.row.col.f32.bf16.bf16.f32 "
                "{%0,%1,%2,%3}, {%4,%5,%6,%7}, {%8,%9}, {%0,%1,%2,%3};"
                : "+f"(acc[nt][0]), "+f"(acc[nt][1]), "+f"(acc[nt][2]), "+f"(acc[nt][3])
                : "r"(ah[0]), "r"(ah[1]), "r"(ah[2]), "r"(ah[3]),
                  "r"(bl[nt][0]), "r"(bl[nt][1]));
            asm volatile(
                "mma.sync.aligned.m16n8k16.row.col.f32.bf16.bf16.f32 "
                "{%0,%1,%2,%3}, {%4,%5,%6,%7}, {%8,%9}, {%0,%1,%2,%3};"
                : "+f"(acc[nt][0]), "+f"(acc[nt][1]), "+f"(acc[nt][2]), "+f"(acc[nt][3])
                : "r"(al[0]), "r"(al[1]), "r"(al[2]), "r"(al[3]),
                  "r"(bh[nt][0]), "r"(bh[nt][1]));
        }
    }

    // ---- Epilogue: add bias, store fp32 ----
    const int g  = lane >> 2;
    const int t2 = (lane & 3) * 2;
    #pragma unroll
    for (int half = 0; half < 2; half++) {
        int r = row0 + m_base + g + half * 8;
        if (r < N) {
            #pragma unroll
            for (int nt = 0; nt < 8; nt++) {
                int col = n_base + nt * 8 + t2;
                float2 o;
                o.x = acc[nt][half * 2 + 0] + __ldg(&b[col]);
                o.y = acc[nt][half * 2 + 1] + __ldg(&b[col + 1]);
                *(float2*)&out[(size_t)r * HD + col] = o;
            }
        }
    }
}

// ---------------------------------------------------------------------------
// CSR build: histogram -> scan -> scatter
// ---------------------------------------------------------------------------
__global__ __launch_bounds__(256) void hist_kernel(const int* __restrict__ dst, int E)
{
    int e = blockIdx.x * blockDim.x + threadIdx.x;
    if (e < E) atomicAdd(&g_count[dst[e]], 1);
}

__global__ __launch_bounds__(1024) void scan1_kernel(int N)
{
    __shared__ int sdata[1024];
    int tid = threadIdx.x;
    int idx = blockIdx.x * 1024 + tid;
    int val = (idx < N) ? g_count[idx] : 0;
    sdata[tid] = val;
    __syncthreads();
    #pragma unroll
    for (int off = 1; off < 1024; off <<= 1) {
        int t = (tid >= off) ? sdata[tid - off] : 0;
        __syncthreads();
        sdata[tid] += t;
        __syncthreads();
    }
    if (idx < N) g_start[idx] = sdata[tid] - val;   // exclusive, partial
    if (tid == 1023) g_bsums[blockIdx.x] = sdata[1023];
}

__global__ void scan2_kernel(int nblocks)
{
    int run = 0;
    for (int i = 0; i < nblocks; i++) {
        int t = g_bsums[i];
        g_bsums[i] = run;
        run += t;
    }
}

__global__ __launch_bounds__(256) void scan3_kernel(int N)
{
    int i = blockIdx.x * blockDim.x + threadIdx.x;
    if (i < N) {
        int s = g_start[i] + g_bsums[i >> 10];
        g_start[i]  = s;
        g_cursor[i] = s;
    }
}

__global__ __launch_bounds__(256) void scatter_kernel(
    const int* __restrict__ src, const int* __restrict__ dst, int E)
{
    int e = blockIdx.x * blockDim.x + threadIdx.x;
    if (e < E) {
        int pos = atomicAdd(&g_cursor[dst[e]], 1);
        g_csr_src[pos] = src[e];
    }
}

// ---------------------------------------------------------------------------
// Gather: one warp per dst node. Q loaded once; wV/z accumulated in regs;
// normalized output written directly (no atomics, no finalize).
// lane covers 4 consecutive channels, head = lane>>2.
// ---------------------------------------------------------------------------
__global__ __launch_bounds__(256) void gather_kernel(
    const float* __restrict__ dis,
    const float* __restrict__ att_w, const float* __restrict__ att_b,
    float* __restrict__ out, int N)
{
    int d = (blockIdx.x * blockDim.x + threadIdx.x) >> 5;
    int lane = threadIdx.x & 31;
    if (d >= N) return;

    int start = g_start[d];
    int cnt   = g_count[d];
    int head  = lane >> 2;

    float4 Q4 = *(const float4*)&g_Q[(size_t)d * HD + lane * 4];
    float bias = __ldg(&dis[d]) * __ldg(&att_w[head]) + __ldg(&att_b[head]);

    float4 acc = make_float4(0.f, 0.f, 0.f, 0.f);
    float z = 0.f;

    for (int base = 0; base < cnt; base += 32) {
        int m = min(32, cnt - base);
        int s_l = (base + lane < cnt) ? g_csr_src[start + base + lane] : 0;

        int s0 = __shfl_sync(0xffffffffu, s_l, 0);
        float4 K4 = *(const float4*)&g_K[(size_t)s0 * HD + lane * 4];
        float4 V4 = *(const float4*)&g_V[(size_t)s0 * HD + lane * 4];

        for (int i = 0; i < m; i++) {
            float4 Kc = K4, Vc = V4;
            if (i + 1 < m) {
                int sn = __shfl_sync(0xffffffffu, s_l, i + 1);
                K4 = *(const float4*)&g_K[(size_t)sn * HD + lane * 4];
                V4 = *(const float4*)&g_V[(size_t)sn * HD + lane * 4];
            }
            float dot = Kc.x * Q4.x + Kc.y * Q4.y + Kc.z * Q4.z + Kc.w * Q4.w;
            dot += __shfl_xor_sync(0xffffffffu, dot, 1);
            dot += __shfl_xor_sync(0xffffffffu, dot, 2);
            float sc = (dot + bias) * 0.25f;
            sc = fminf(fmaxf(sc, -5.f), 5.f);
            float w = expf(sc);
            acc.x += Vc.x * w;
            acc.y += Vc.y * w;
            acc.z += Vc.z * w;
            acc.w += Vc.w * w;
            z += w;
        }
    }

    float inv = 1.0f / z;
    float4 o = make_float4(acc.x * inv, acc.y * inv, acc.z * inv, acc.w * inv);
    *(float4*)&out[(size_t)d * HD + lane * 4] = o;
}

// ---------------------------------------------------------------------------
extern "C" void kernel_launch(void* const* d_in, const int* in_sizes, int n_in,
                              void* d_out, int out_size)
{
    const float* h     = (const float*)d_in[0];
    const float* dis   = (const float*)d_in[1];
    const float* Wq    = (const float*)d_in[2];
    const float* bq    = (const float*)d_in[3];
    const float* Wk    = (const float*)d_in[4];
    const float* bk    = (const float*)d_in[5];
    const float* Wv    = (const float*)d_in[6];
    const float* bv    = (const float*)d_in[7];
    const float* att_w = (const float*)d_in[8];
    const float* att_b = (const float*)d_in[9];
    const int*   src   = (const int*)d_in[10];
    const int*   dst   = (const int*)d_in[11];

    int N = in_sizes[1];
    int E = in_sizes[10];
    float* out = (float*)d_out;

    // ---- QKV projections (tensor cores) ----
    size_t smem_bytes = (size_t)(64 + 64 + 128 + 128) * TS * sizeof(unsigned short);
    cudaFuncSetAttribute(qkv_mma_kernel,
                         cudaFuncAttributeMaxDynamicSharedMemorySize,
                         (int)smem_bytes);
    dim3 qkv_grid((N + 63) / 64, 3);
    qkv_mma_kernel<<<qkv_grid, 256, smem_bytes>>>(h, Wq, bq, Wk, bk, Wv, bv, N);

    // ---- CSR build ----
    void* cptr = nullptr;
    cudaGetSymbolAddress(&cptr, g_count);
    cudaMemsetAsync(cptr, 0, (size_t)N * sizeof(int));
    hist_kernel<<<(E + 255) / 256, 256>>>(dst, E);
    int nsb = (N + 1023) / 1024;
    scan1_kernel<<<nsb, 1024>>>(N);
    scan2_kernel<<<1, 1>>>(nsb);
    scan3_kernel<<<(N + 255) / 256, 256>>>(N);
    scatter_kernel<<<(E + 255) / 256, 256>>>(src, dst, E);

    // ---- Gather + normalize (one warp per dst) ----
    gather_kernel<<<((size_t)N * 32 + 255) / 256, 256>>>(dis, att_w, att_b, out, N);
}

// round 5
// speedup vs baseline: 2.1938x; 1.1066x over previous
#include <cuda_runtime.h>
#include <cuda_bf16.h>
#include <math.h>

#define MAXN 50000
#define MAXE 800000
#define HD 128
#define NHEAD 8
#define TS 136   // smem tile stride in bf16 elements (272B rows: conflict-free ldmatrix)

__device__ float g_Q[(size_t)MAXN * HD];
__device__ float g_K[(size_t)MAXN * HD];
__device__ float g_V[(size_t)MAXN * HD];
__device__ int   g_count[MAXN];
__device__ int   g_start[MAXN];
__device__ int   g_cursor[MAXN];
__device__ int   g_csr_src[MAXE];
__device__ int   g_total[1];

// ---------------------------------------------------------------------------
// QKV projection via bf16 tensor cores, fused 2-term split, W-resident:
// each block splits W once into smem (hi/lo), then grid-strides over 64-row
// h tiles. acc += Ahi*Bhi + Ahi*Blo + Alo*Bhi in one k-loop.
// ---------------------------------------------------------------------------
extern __shared__ unsigned short smem_bf[];

__global__ __launch_bounds__(256, 2) void qkv_mma_kernel(
    const float* __restrict__ h,
    const float* __restrict__ Wq, const float* __restrict__ bq,
    const float* __restrict__ Wk, const float* __restrict__ bk,
    const float* __restrict__ Wv, const float* __restrict__ bv,
    int N, int ntiles)
{
    const float* W;
    const float* b;
    float* out;
    if (blockIdx.y == 0)      { W = Wq; b = bq; out = g_Q; }
    else if (blockIdx.y == 1) { W = Wk; b = bk; out = g_K; }
    else                      { W = Wv; b = bv; out = g_V; }

    unsigned short* A_hi = smem_bf;                 // 64 x TS
    unsigned short* A_lo = A_hi + 64 * TS;          // 64 x TS
    unsigned short* B_hi = A_lo + 64 * TS;          // 128 x TS
    unsigned short* B_lo = B_hi + 128 * TS;         // 128 x TS

    const int tid  = threadIdx.x;
    const int warp = tid >> 5;
    const int lane = tid & 31;
    const int wm = warp & 3;           // m16 tile index
    const int wn = warp >> 2;          // n64 half
    const int m_base = wm * 16;
    const int n_base = wn * 64;

    // ---- Load + split W once per block ----
    #pragma unroll
    for (int i = 0; i < 16; i++) {
        int idx = tid + i * 256;
        int r   = idx >> 5;
        int c4  = idx & 31;
        float4 v = *(const float4*)&W[(size_t)r * HD + c4 * 4];
        float vv[4] = {v.x, v.y, v.z, v.w};
        unsigned short hs[4], ls[4];
        #pragma unroll
        for (int j = 0; j < 4; j++) {
            __nv_bfloat16 hb = __float2bfloat16(vv[j]);
            float lf = vv[j] - __bfloat162float(hb);
            __nv_bfloat16 lb = __float2bfloat16(lf);
            hs[j] = __bfloat16_as_ushort(hb);
            ls[j] = __bfloat16_as_ushort(lb);
        }
        uint2 ph, pl;
        ph.x = (unsigned)hs[0] | ((unsigned)hs[1] << 16);
        ph.y = (unsigned)hs[2] | ((unsigned)hs[3] << 16);
        pl.x = (unsigned)ls[0] | ((unsigned)ls[1] << 16);
        pl.y = (unsigned)ls[2] | ((unsigned)ls[3] << 16);
        *(uint2*)&B_hi[r * TS + c4 * 4] = ph;
        *(uint2*)&B_lo[r * TS + c4 * 4] = pl;
    }

    // Preload bias for this thread's 16 output columns
    const int t2 = (lane & 3) * 2;
    float2 bb[8];
    #pragma unroll
    for (int nt = 0; nt < 8; nt++) {
        int col = n_base + nt * 8 + t2;
        bb[nt].x = __ldg(&b[col]);
        bb[nt].y = __ldg(&b[col + 1]);
    }

    const int a_row  = m_base + (lane & 15);
    const int a_coff = (lane >> 4) * 8;
    const int b_roff = (lane & 7) + ((lane >> 3) & 1) * 8;
    const int b_col  = n_base + (lane >> 4) * 8;
    const int g      = lane >> 2;

    for (int tile = blockIdx.x; tile < ntiles; tile += gridDim.x) {
        const int row0 = tile * 64;

        __syncthreads();   // prior tile's MMAs done reading A smem (also covers W writes)

        // ---- Load h tile (64x128 fp32 = 2048 float4) -> split to bf16 hi/lo ----
        #pragma unroll
        for (int i = 0; i < 8; i++) {
            int idx = tid + i * 256;          // 0..2047 float4 slots
            int r   = idx >> 5;               // row 0..63
            int c4  = idx & 31;               // float4 col
            float4 v = make_float4(0.f, 0.f, 0.f, 0.f);
            int gr = row0 + r;
            if (gr < N) v = *(const float4*)&h[(size_t)gr * HD + c4 * 4];
            float vv[4] = {v.x, v.y, v.z, v.w};
            unsigned short hs[4], ls[4];
            #pragma unroll
            for (int j = 0; j < 4; j++) {
                __nv_bfloat16 hb = __float2bfloat16(vv[j]);
                float lf = vv[j] - __bfloat162float(hb);
                __nv_bfloat16 lb = __float2bfloat16(lf);
                hs[j] = __bfloat16_as_ushort(hb);
                ls[j] = __bfloat16_as_ushort(lb);
            }
            uint2 ph, pl;
            ph.x = (unsigned)hs[0] | ((unsigned)hs[1] << 16);
            ph.y = (unsigned)hs[2] | ((unsigned)hs[3] << 16);
            pl.x = (unsigned)ls[0] | ((unsigned)ls[1] << 16);
            pl.y = (unsigned)ls[2] | ((unsigned)ls[3] << 16);
            *(uint2*)&A_hi[r * TS + c4 * 4] = ph;
            *(uint2*)&A_lo[r * TS + c4 * 4] = pl;
        }
        __syncthreads();

        float acc[8][4];
        #pragma unroll
        for (int nt = 0; nt < 8; nt++)
            #pragma unroll
            for (int q = 0; q < 4; q++) acc[nt][q] = 0.f;

        #pragma unroll
        for (int ks = 0; ks < 8; ks++) {
            const int k0 = ks * 16;
            unsigned ah[4], al[4];
            {
                unsigned addr = (unsigned)__cvta_generic_to_shared(
                    &A_hi[a_row * TS + k0 + a_coff]);
                asm volatile(
                    "ldmatrix.sync.aligned.m8n8.x4.shared.b16 {%0,%1,%2,%3}, [%4];"
                    : "=r"(ah[0]), "=r"(ah[1]), "=r"(ah[2]), "=r"(ah[3]) : "r"(addr));
                addr = (unsigned)__cvta_generic_to_shared(
                    &A_lo[a_row * TS + k0 + a_coff]);
                asm volatile(
                    "ldmatrix.sync.aligned.m8n8.x4.shared.b16 {%0,%1,%2,%3}, [%4];"
                    : "=r"(al[0]), "=r"(al[1]), "=r"(al[2]), "=r"(al[3]) : "r"(addr));
            }
            unsigned bh[8][2], bl[8][2];
            #pragma unroll
            for (int np = 0; np < 4; np++) {
                unsigned addr = (unsigned)__cvta_generic_to_shared(
                    &B_hi[(k0 + b_roff) * TS + b_col + np * 16]);
                unsigned r0, r1, r2, r3;
                asm volatile(
                    "ldmatrix.sync.aligned.m8n8.x4.trans.shared.b16 {%0,%1,%2,%3}, [%4];"
                    : "=r"(r0), "=r"(r1), "=r"(r2), "=r"(r3) : "r"(addr));
                bh[np * 2][0] = r0; bh[np * 2][1] = r1;
                bh[np * 2 + 1][0] = r2; bh[np * 2 + 1][1] = r3;
                addr = (unsigned)__cvta_generic_to_shared(
                    &B_lo[(k0 + b_roff) * TS + b_col + np * 16]);
                asm volatile(
                    "ldmatrix.sync.aligned.m8n8.x4.trans.shared.b16 {%0,%1,%2,%3}, [%4];"
                    : "=r"(r0), "=r"(r1), "=r"(r2), "=r"(r3) : "r"(addr));
                bl[np * 2][0] = r0; bl[np * 2][1] = r1;
                bl[np * 2 + 1][0] = r2; bl[np * 2 + 1][1] = r3;
            }
            #pragma unroll
            for (int nt = 0; nt < 8; nt++) {
                asm volatile(
                    "mma.sync.aligned.m16n8k16.row.col.f32.bf16.bf16.f32 "
                    "{%0,%1,%2,%3}, {%4,%5,%6,%7}, {%8,%9}, {%0,%1,%2,%3};"
                    : "+f"(acc[nt][0]), "+f"(acc[nt][1]), "+f"(acc[nt][2]), "+f"(acc[nt][3])
                    : "r"(ah[0]), "r"(ah[1]), "r"(ah[2]), "r"(ah[3]),
                      "r"(bh[nt][0]), "r"(bh[nt][1]));
                asm volatile(
                    "mma.sync.aligned.m16n8k16.row.col.f32.bf16.bf16.f32 "
                    "{%0,%1,%2,%3}, {%4,%5,%6,%7}, {%8,%9}, {%0,%1,%2,%3};"
                    : "+f"(acc[nt][0]), "+f"(acc[nt][1]), "+f"(acc[nt][2]), "+f"(acc[nt][3])
                    : "r"(ah[0]), "r"(ah[1]), "r"(ah[2]), "r"(ah[3]),
                      "r"(bl[nt][0]), "r"(bl[nt][1]));
                asm volatile(
                    "mma.sync.aligned.m16n8k16.row.col.f32.bf16.bf16.f32 "
                    "{%0,%1,%2,%3}, {%4,%5,%6,%7}, {%8,%9}, {%0,%1,%2,%3};"
                    : "+f"(acc[nt][0]), "+f"(acc[nt][1]), "+f"(acc[nt][2]), "+f"(acc[nt][3])
                    : "r"(al[0]), "r"(al[1]), "r"(al[2]), "r"(al[3]),
                      "r"(bh[nt][0]), "r"(bh[nt][1]));
            }
        }

        // ---- Epilogue ----
        #pragma unroll
        for (int half = 0; half < 2; half++) {
            int r = row0 + m_base + g + half * 8;
            if (r < N) {
                #pragma unroll
                for (int nt = 0; nt < 8; nt++) {
                    int col = n_base + nt * 8 + t2;
                    float2 o;
                    o.x = acc[nt][half * 2 + 0] + bb[nt].x;
                    o.y = acc[nt][half * 2 + 1] + bb[nt].y;
                    *(float2*)&out[(size_t)r * HD + col] = o;
                }
            }
        }
    }
}

// ---------------------------------------------------------------------------
// CSR build without scans: hist -> warp-aggregated start assignment -> scatter.
// Segment order across nodes is arbitrary (irrelevant for correctness).
// ---------------------------------------------------------------------------
__global__ __launch_bounds__(256) void hist_kernel(const int* __restrict__ dst, int E)
{
    int e = blockIdx.x * blockDim.x + threadIdx.x;
    if (e < E) atomicAdd(&g_count[dst[e]], 1);
}

__global__ __launch_bounds__(256) void assign_starts_kernel(int N)
{
    int i = blockIdx.x * blockDim.x + threadIdx.x;
    int lane = threadIdx.x & 31;
    int c = (i < N) ? g_count[i] : 0;

    // warp inclusive prefix sum
    int p = c;
    #pragma unroll
    for (int off = 1; off < 32; off <<= 1) {
        int t = __shfl_up_sync(0xffffffffu, p, off);
        if (lane >= off) p += t;
    }
    int warp_total = __shfl_sync(0xffffffffu, p, 31);
    int base = 0;
    if (lane == 0) base = atomicAdd(&g_total[0], warp_total);
    base = __shfl_sync(0xffffffffu, base, 0);

    if (i < N) {
        int s = base + p - c;
        g_start[i]  = s;
        g_cursor[i] = s;
    }
}

__global__ __launch_bounds__(256) void scatter_kernel(
    const int* __restrict__ src, const int* __restrict__ dst, int E)
{
    int e = blockIdx.x * blockDim.x + threadIdx.x;
    if (e < E) {
        int pos = atomicAdd(&g_cursor[dst[e]], 1);
        g_csr_src[pos] = src[e];
    }
}

// ---------------------------------------------------------------------------
// Gather: one warp per dst node; wV/z in registers; direct normalized store.
// ---------------------------------------------------------------------------
__global__ __launch_bounds__(256) void gather_kernel(
    const float* __restrict__ dis,
    const float* __restrict__ att_w, const float* __restrict__ att_b,
    float* __restrict__ out, int N)
{
    int d = (blockIdx.x * blockDim.x + threadIdx.x) >> 5;
    int lane = threadIdx.x & 31;
    if (d >= N) return;

    int start = g_start[d];
    int cnt   = g_count[d];
    int head  = lane >> 2;

    float4 Q4 = *(const float4*)&g_Q[(size_t)d * HD + lane * 4];
    float bias = __ldg(&dis[d]) * __ldg(&att_w[head]) + __ldg(&att_b[head]);

    float4 acc = make_float4(0.f, 0.f, 0.f, 0.f);
    float z = 0.f;

    for (int base = 0; base < cnt; base += 32) {
        int m = min(32, cnt - base);
        int s_l = (base + lane < cnt) ? g_csr_src[start + base + lane] : 0;

        int s0 = __shfl_sync(0xffffffffu, s_l, 0);
        float4 K4 = *(const float4*)&g_K[(size_t)s0 * HD + lane * 4];
        float4 V4 = *(const float4*)&g_V[(size_t)s0 * HD + lane * 4];

        for (int i = 0; i < m; i++) {
            float4 Kc = K4, Vc = V4;
            if (i + 1 < m) {
                int sn = __shfl_sync(0xffffffffu, s_l, i + 1);
                K4 = *(const float4*)&g_K[(size_t)sn * HD + lane * 4];
                V4 = *(const float4*)&g_V[(size_t)sn * HD + lane * 4];
            }
            float dot = Kc.x * Q4.x + Kc.y * Q4.y + Kc.z * Q4.z + Kc.w * Q4.w;
            dot += __shfl_xor_sync(0xffffffffu, dot, 1);
            dot += __shfl_xor_sync(0xffffffffu, dot, 2);
            float sc = (dot + bias) * 0.25f;
            sc = fminf(fmaxf(sc, -5.f), 5.f);
            float w = expf(sc);
            acc.x += Vc.x * w;
            acc.y += Vc.y * w;
            acc.z += Vc.z * w;
            acc.w += Vc.w * w;
            z += w;
        }
    }

    float inv = 1.0f / z;
    float4 o = make_float4(acc.x * inv, acc.y * inv, acc.z * inv, acc.w * inv);
    *(float4*)&out[(size_t)d * HD + lane * 4] = o;
}

// ---------------------------------------------------------------------------
extern "C" void kernel_launch(void* const* d_in, const int* in_sizes, int n_in,
                              void* d_out, int out_size)
{
    const float* h     = (const float*)d_in[0];
    const float* dis   = (const float*)d_in[1];
    const float* Wq    = (const float*)d_in[2];
    const float* bq    = (const float*)d_in[3];
    const float* Wk    = (const float*)d_in[4];
    const float* bk    = (const float*)d_in[5];
    const float* Wv    = (const float*)d_in[6];
    const float* bv    = (const float*)d_in[7];
    const float* att_w = (const float*)d_in[8];
    const float* att_b = (const float*)d_in[9];
    const int*   src   = (const int*)d_in[10];
    const int*   dst   = (const int*)d_in[11];

    int N = in_sizes[1];
    int E = in_sizes[10];
    float* out = (float*)d_out;

    // ---- QKV projections (tensor cores, W-resident blocks) ----
    size_t smem_bytes = (size_t)(64 + 64 + 128 + 128) * TS * sizeof(unsigned short);
    cudaFuncSetAttribute(qkv_mma_kernel,
                         cudaFuncAttributeMaxDynamicSharedMemorySize,
                         (int)smem_bytes);
    int ntiles = (N + 63) / 64;
    int nblocks_x = 98;                         // ~8 tiles per block, 294 total blocks
    dim3 qkv_grid(nblocks_x, 3);
    qkv_mma_kernel<<<qkv_grid, 256, smem_bytes>>>(h, Wq, bq, Wk, bk, Wv, bv, N, ntiles);

    // ---- CSR build (scan-free) ----
    void* cptr = nullptr;
    cudaGetSymbolAddress(&cptr, g_count);
    cudaMemsetAsync(cptr, 0, (size_t)N * sizeof(int));
    void* tptr = nullptr;
    cudaGetSymbolAddress(&tptr, g_total);
    cudaMemsetAsync(tptr, 0, sizeof(int));
    hist_kernel<<<(E + 255) / 256, 256>>>(dst, E);
    assign_starts_kernel<<<(N + 255) / 256, 256>>>(N);
    scatter_kernel<<<(E + 255) / 256, 256>>>(src, dst, E);

    // ---- Gather + normalize (one warp per dst) ----
    gather_kernel<<<((size_t)N * 32 + 255) / 256, 256>>>(dis, att_w, att_b, out, N);
}

// round 6
// speedup vs baseline: 2.3045x; 1.0505x over previous
#include <cuda_runtime.h>
#include <cuda_bf16.h>
#include <math.h>

#define MAXN 50000
#define MAXE 800000
#define HD 128
#define NHEAD 8
#define TS 136   // smem tile stride in bf16 elements (272B rows: conflict-free ldmatrix)

__device__ float g_Q[(size_t)MAXN * HD];
__device__ float g_K[(size_t)MAXN * HD];
__device__ float g_V[(size_t)MAXN * HD];
__device__ int   g_count[MAXN];
__device__ int   g_start[MAXN];
__device__ int   g_cursor[MAXN];
__device__ int   g_csr_src[MAXE];
__device__ int   g_total[1];

// ---------------------------------------------------------------------------
// QKV projection via bf16 tensor cores, fused 2-term split, W-resident:
// each block splits W once into smem (hi/lo), then grid-strides over 64-row
// h tiles. acc += Ahi*Bhi + Ahi*Blo + Alo*Bhi in one k-loop.
// ---------------------------------------------------------------------------
extern __shared__ unsigned short smem_bf[];

__global__ __launch_bounds__(256, 2) void qkv_mma_kernel(
    const float* __restrict__ h,
    const float* __restrict__ Wq, const float* __restrict__ bq,
    const float* __restrict__ Wk, const float* __restrict__ bk,
    const float* __restrict__ Wv, const float* __restrict__ bv,
    int N, int ntiles)
{
    const float* W;
    const float* b;
    float* out;
    if (blockIdx.y == 0)      { W = Wq; b = bq; out = g_Q; }
    else if (blockIdx.y == 1) { W = Wk; b = bk; out = g_K; }
    else                      { W = Wv; b = bv; out = g_V; }

    unsigned short* A_hi = smem_bf;                 // 64 x TS
    unsigned short* A_lo = A_hi + 64 * TS;          // 64 x TS
    unsigned short* B_hi = A_lo + 64 * TS;          // 128 x TS
    unsigned short* B_lo = B_hi + 128 * TS;         // 128 x TS

    const int tid  = threadIdx.x;
    const int warp = tid >> 5;
    const int lane = tid & 31;
    const int wm = warp & 3;           // m16 tile index
    const int wn = warp >> 2;          // n64 half
    const int m_base = wm * 16;
    const int n_base = wn * 64;

    // ---- Load + split W once per block ----
    #pragma unroll
    for (int i = 0; i < 16; i++) {
        int idx = tid + i * 256;
        int r   = idx >> 5;
        int c4  = idx & 31;
        float4 v = *(const float4*)&W[(size_t)r * HD + c4 * 4];
        float vv[4] = {v.x, v.y, v.z, v.w};
        unsigned short hs[4], ls[4];
        #pragma unroll
        for (int j = 0; j < 4; j++) {
            __nv_bfloat16 hb = __float2bfloat16(vv[j]);
            float lf = vv[j] - __bfloat162float(hb);
            __nv_bfloat16 lb = __float2bfloat16(lf);
            hs[j] = __bfloat16_as_ushort(hb);
            ls[j] = __bfloat16_as_ushort(lb);
        }
        uint2 ph, pl;
        ph.x = (unsigned)hs[0] | ((unsigned)hs[1] << 16);
        ph.y = (unsigned)hs[2] | ((unsigned)hs[3] << 16);
        pl.x = (unsigned)ls[0] | ((unsigned)ls[1] << 16);
        pl.y = (unsigned)ls[2] | ((unsigned)ls[3] << 16);
        *(uint2*)&B_hi[r * TS + c4 * 4] = ph;
        *(uint2*)&B_lo[r * TS + c4 * 4] = pl;
    }

    // Preload bias for this thread's 16 output columns
    const int t2 = (lane & 3) * 2;
    float2 bb[8];
    #pragma unroll
    for (int nt = 0; nt < 8; nt++) {
        int col = n_base + nt * 8 + t2;
        bb[nt].x = __ldg(&b[col]);
        bb[nt].y = __ldg(&b[col + 1]);
    }

    const int a_row  = m_base + (lane & 15);
    const int a_coff = (lane >> 4) * 8;
    const int b_roff = (lane & 7) + ((lane >> 3) & 1) * 8;
    const int b_col  = n_base + (lane >> 4) * 8;
    const int g      = lane >> 2;

    for (int tile = blockIdx.x; tile < ntiles; tile += gridDim.x) {
        const int row0 = tile * 64;

        __syncthreads();   // prior tile's MMAs done reading A smem (also covers W writes)

        // ---- Load h tile (64x128 fp32 = 2048 float4) -> split to bf16 hi/lo ----
        #pragma unroll
        for (int i = 0; i < 8; i++) {
            int idx = tid + i * 256;          // 0..2047 float4 slots
            int r   = idx >> 5;               // row 0..63
            int c4  = idx & 31;               // float4 col
            float4 v = make_float4(0.f, 0.f, 0.f, 0.f);
            int gr = row0 + r;
            if (gr < N) v = *(const float4*)&h[(size_t)gr * HD + c4 * 4];
            float vv[4] = {v.x, v.y, v.z, v.w};
            unsigned short hs[4], ls[4];
            #pragma unroll
            for (int j = 0; j < 4; j++) {
                __nv_bfloat16 hb = __float2bfloat16(vv[j]);
                float lf = vv[j] - __bfloat162float(hb);
                __nv_bfloat16 lb = __float2bfloat16(lf);
                hs[j] = __bfloat16_as_ushort(hb);
                ls[j] = __bfloat16_as_ushort(lb);
            }
            uint2 ph, pl;
            ph.x = (unsigned)hs[0] | ((unsigned)hs[1] << 16);
            ph.y = (unsigned)hs[2] | ((unsigned)hs[3] << 16);
            pl.x = (unsigned)ls[0] | ((unsigned)ls[1] << 16);
            pl.y = (unsigned)ls[2] | ((unsigned)ls[3] << 16);
            *(uint2*)&A_hi[r * TS + c4 * 4] = ph;
            *(uint2*)&A_lo[r * TS + c4 * 4] = pl;
        }
        __syncthreads();

        float acc[8][4];
        #pragma unroll
        for (int nt = 0; nt < 8; nt++)
            #pragma unroll
            for (int q = 0; q < 4; q++) acc[nt][q] = 0.f;

        #pragma unroll
        for (int ks = 0; ks < 8; ks++) {
            const int k0 = ks * 16;
            unsigned ah[4], al[4];
            {
                unsigned addr = (unsigned)__cvta_generic_to_shared(
                    &A_hi[a_row * TS + k0 + a_coff]);
                asm volatile(
                    "ldmatrix.sync.aligned.m8n8.x4.shared.b16 {%0,%1,%2,%3}, [%4];"
                    : "=r"(ah[0]), "=r"(ah[1]), "=r"(ah[2]), "=r"(ah[3]) : "r"(addr));
                addr = (unsigned)__cvta_generic_to_shared(
                    &A_lo[a_row * TS + k0 + a_coff]);
                asm volatile(
                    "ldmatrix.sync.aligned.m8n8.x4.shared.b16 {%0,%1,%2,%3}, [%4];"
                    : "=r"(al[0]), "=r"(al[1]), "=r"(al[2]), "=r"(al[3]) : "r"(addr));
            }
            unsigned bh[8][2], bl[8][2];
            #pragma unroll
            for (int np = 0; np < 4; np++) {
                unsigned addr = (unsigned)__cvta_generic_to_shared(
                    &B_hi[(k0 + b_roff) * TS + b_col + np * 16]);
                unsigned r0, r1, r2, r3;
                asm volatile(
                    "ldmatrix.sync.aligned.m8n8.x4.trans.shared.b16 {%0,%1,%2,%3}, [%4];"
                    : "=r"(r0), "=r"(r1), "=r"(r2), "=r"(r3) : "r"(addr));
                bh[np * 2][0] = r0; bh[np * 2][1] = r1;
                bh[np * 2 + 1][0] = r2; bh[np * 2 + 1][1] = r3;
                addr = (unsigned)__cvta_generic_to_shared(
                    &B_lo[(k0 + b_roff) * TS + b_col + np * 16]);
                asm volatile(
                    "ldmatrix.sync.aligned.m8n8.x4.trans.shared.b16 {%0,%1,%2,%3}, [%4];"
                    : "=r"(r0), "=r"(r1), "=r"(r2), "=r"(r3) : "r"(addr));
                bl[np * 2][0] = r0; bl[np * 2][1] = r1;
                bl[np * 2 + 1][0] = r2; bl[np * 2 + 1][1] = r3;
            }
            #pragma unroll
            for (int nt = 0; nt < 8; nt++) {
                asm volatile(
                    "mma.sync.aligned.m16n8k16.row.col.f32.bf16.bf16.f32 "
                    "{%0,%1,%2,%3}, {%4,%5,%6,%7}, {%8,%9}, {%0,%1,%2,%3};"
                    : "+f"(acc[nt][0]), "+f"(acc[nt][1]), "+f"(acc[nt][2]), "+f"(acc[nt][3])
                    : "r"(ah[0]), "r"(ah[1]), "r"(ah[2]), "r"(ah[3]),
                      "r"(bh[nt][0]), "r"(bh[nt][1]));
                asm volatile(
                    "mma.sync.aligned.m16n8k16.row.col.f32.bf16.bf16.f32 "
                    "{%0,%1,%2,%3}, {%4,%5,%6,%7}, {%8,%9}, {%0,%1,%2,%3};"
                    : "+f"(acc[nt][0]), "+f"(acc[nt][1]), "+f"(acc[nt][2]), "+f"(acc[nt][3])
                    : "r"(ah[0]), "r"(ah[1]), "r"(ah[2]), "r"(ah[3]),
                      "r"(bl[nt][0]), "r"(bl[nt][1]));
                asm volatile(
                    "mma.sync.aligned.m16n8k16.row.col.f32.bf16.bf16.f32 "
                    "{%0,%1,%2,%3}, {%4,%5,%6,%7}, {%8,%9}, {%0,%1,%2,%3};"
                    : "+f"(acc[nt][0]), "+f"(acc[nt][1]), "+f"(acc[nt][2]), "+f"(acc[nt][3])
                    : "r"(al[0]), "r"(al[1]), "r"(al[2]), "r"(al[3]),
                      "r"(bh[nt][0]), "r"(bh[nt][1]));
            }
        }

        // ---- Epilogue ----
        #pragma unroll
        for (int half = 0; half < 2; half++) {
            int r = row0 + m_base + g + half * 8;
            if (r < N) {
                #pragma unroll
                for (int nt = 0; nt < 8; nt++) {
                    int col = n_base + nt * 8 + t2;
                    float2 o;
                    o.x = acc[nt][half * 2 + 0] + bb[nt].x;
                    o.y = acc[nt][half * 2 + 1] + bb[nt].y;
                    *(float2*)&out[(size_t)r * HD + col] = o;
                }
            }
        }
    }
}

// ---------------------------------------------------------------------------
// CSR build without scans: hist -> warp-aggregated start assignment -> scatter.
// ---------------------------------------------------------------------------
__global__ __launch_bounds__(256) void hist_kernel(const int* __restrict__ dst, int E)
{
    int e = blockIdx.x * blockDim.x + threadIdx.x;
    if (e < E) atomicAdd(&g_count[dst[e]], 1);
}

__global__ __launch_bounds__(256) void assign_starts_kernel(int N)
{
    int i = blockIdx.x * blockDim.x + threadIdx.x;
    int lane = threadIdx.x & 31;
    int c = (i < N) ? g_count[i] : 0;

    int p = c;
    #pragma unroll
    for (int off = 1; off < 32; off <<= 1) {
        int t = __shfl_up_sync(0xffffffffu, p, off);
        if (lane >= off) p += t;
    }
    int warp_total = __shfl_sync(0xffffffffu, p, 31);
    int base = 0;
    if (lane == 0) base = atomicAdd(&g_total[0], warp_total);
    base = __shfl_sync(0xffffffffu, base, 0);

    if (i < N) {
        int s = base + p - c;
        g_start[i]  = s;
        g_cursor[i] = s;
    }
}

__global__ __launch_bounds__(256) void scatter_kernel(
    const int* __restrict__ src, const int* __restrict__ dst, int E)
{
    int e = blockIdx.x * blockDim.x + threadIdx.x;
    if (e < E) {
        int pos = atomicAdd(&g_cursor[dst[e]], 1);
        g_csr_src[pos] = src[e];
    }
}

// ---------------------------------------------------------------------------
// Gather: one warp per dst node; wV/z in registers; direct normalized store.
// ---------------------------------------------------------------------------
__global__ __launch_bounds__(256) void gather_kernel(
    const float* __restrict__ dis,
    const float* __restrict__ att_w, const float* __restrict__ att_b,
    float* __restrict__ out, int N)
{
    int d = (blockIdx.x * blockDim.x + threadIdx.x) >> 5;
    int lane = threadIdx.x & 31;
    if (d >= N) return;

    int start = g_start[d];
    int cnt   = g_count[d];
    int head  = lane >> 2;

    float4 Q4 = *(const float4*)&g_Q[(size_t)d * HD + lane * 4];
    float bias = __ldg(&dis[d]) * __ldg(&att_w[head]) + __ldg(&att_b[head]);

    float4 acc = make_float4(0.f, 0.f, 0.f, 0.f);
    float z = 0.f;

    for (int base = 0; base < cnt; base += 32) {
        int m = min(32, cnt - base);
        int s_l = (base + lane < cnt) ? g_csr_src[start + base + lane] : 0;

        int s0 = __shfl_sync(0xffffffffu, s_l, 0);
        float4 K4 = *(const float4*)&g_K[(size_t)s0 * HD + lane * 4];
        float4 V4 = *(const float4*)&g_V[(size_t)s0 * HD + lane * 4];

        for (int i = 0; i < m; i++) {
            float4 Kc = K4, Vc = V4;
            if (i + 1 < m) {
                int sn = __shfl_sync(0xffffffffu, s_l, i + 1);
                K4 = *(const float4*)&g_K[(size_t)sn * HD + lane * 4];
                V4 = *(const float4*)&g_V[(size_t)sn * HD + lane * 4];
            }
            float dot = Kc.x * Q4.x + Kc.y * Q4.y + Kc.z * Q4.z + Kc.w * Q4.w;
            dot += __shfl_xor_sync(0xffffffffu, dot, 1);
            dot += __shfl_xor_sync(0xffffffffu, dot, 2);
            float sc = (dot + bias) * 0.25f;
            sc = fminf(fmaxf(sc, -5.f), 5.f);
            float w = expf(sc);
            acc.x += Vc.x * w;
            acc.y += Vc.y * w;
            acc.z += Vc.z * w;
            acc.w += Vc.w * w;
            z += w;
        }
    }

    float inv = 1.0f / z;
    float4 o = make_float4(acc.x * inv, acc.y * inv, acc.z * inv, acc.w * inv);
    *(float4*)&out[(size_t)d * HD + lane * 4] = o;
}

// ---------------------------------------------------------------------------
extern "C" void kernel_launch(void* const* d_in, const int* in_sizes, int n_in,
                              void* d_out, int out_size)
{
    const float* h     = (const float*)d_in[0];
    const float* dis   = (const float*)d_in[1];
    const float* Wq    = (const float*)d_in[2];
    const float* bq    = (const float*)d_in[3];
    const float* Wk    = (const float*)d_in[4];
    const float* bk    = (const float*)d_in[5];
    const float* Wv    = (const float*)d_in[6];
    const float* bv    = (const float*)d_in[7];
    const float* att_w = (const float*)d_in[8];
    const float* att_b = (const float*)d_in[9];
    const int*   src   = (const int*)d_in[10];
    const int*   dst   = (const int*)d_in[11];

    int N = in_sizes[1];
    int E = in_sizes[10];
    float* out = (float*)d_out;

    // One-time host-side resources (no device memory involved)
    static cudaStream_t s2 = nullptr;
    static cudaEvent_t ev_fork = nullptr, ev_join = nullptr;
    static bool inited = false;
    if (!inited) {
        cudaStreamCreateWithFlags(&s2, cudaStreamNonBlocking);
        cudaEventCreateWithFlags(&ev_fork, cudaEventDisableTiming);
        cudaEventCreateWithFlags(&ev_join, cudaEventDisableTiming);
        size_t smem_bytes = (size_t)(64 + 64 + 128 + 128) * TS * sizeof(unsigned short);
        cudaFuncSetAttribute(qkv_mma_kernel,
                             cudaFuncAttributeMaxDynamicSharedMemorySize,
                             (int)smem_bytes);
        inited = true;
    }
    size_t smem_bytes = (size_t)(64 + 64 + 128 + 128) * TS * sizeof(unsigned short);

    // ---- Fork: CSR build on s2 runs concurrently with QKV on main stream ----
    cudaEventRecord(ev_fork, 0);
    cudaStreamWaitEvent(s2, ev_fork, 0);

    // Stream s2: CSR build (independent of QKV)
    void* cptr = nullptr;
    cudaGetSymbolAddress(&cptr, g_count);
    cudaMemsetAsync(cptr, 0, (size_t)N * sizeof(int), s2);
    void* tptr = nullptr;
    cudaGetSymbolAddress(&tptr, g_total);
    cudaMemsetAsync(tptr, 0, sizeof(int), s2);
    hist_kernel<<<(E + 255) / 256, 256, 0, s2>>>(dst, E);
    assign_starts_kernel<<<(N + 255) / 256, 256, 0, s2>>>(N);
    scatter_kernel<<<(E + 255) / 256, 256, 0, s2>>>(src, dst, E);
    cudaEventRecord(ev_join, s2);

    // Main stream: QKV projections (tensor cores, W-resident blocks)
    int ntiles = (N + 63) / 64;
    dim3 qkv_grid(98, 3);
    qkv_mma_kernel<<<qkv_grid, 256, smem_bytes>>>(h, Wq, bq, Wk, bk, Wv, bv, N, ntiles);

    // ---- Join, then gather + normalize ----
    cudaStreamWaitEvent(0, ev_join, 0);
    gather_kernel<<<((size_t)N * 32 + 255) / 256, 256>>>(dis, att_w, att_b, out, N);
}

// round 7
// speedup vs baseline: 2.4716x; 1.0725x over previous
#include <cuda_runtime.h>
#include <cuda_bf16.h>
#include <cuda_fp16.h>
#include <math.h>

#define MAXN 50000
#define MAXE 800000
#define HD 128
#define NHEAD 8
#define TS 136   // smem tile stride in bf16 elements (272B rows: conflict-free ldmatrix)

__device__ float  g_Q[(size_t)MAXN * HD];
__device__ __half g_Kh[(size_t)MAXN * HD];
__device__ __half g_Vh[(size_t)MAXN * HD];
__device__ int    g_count[MAXN];
__device__ int    g_start[MAXN];
__device__ int    g_cursor[MAXN];
__device__ int    g_csr_src[MAXE];
__device__ int    g_total[1];

// ---------------------------------------------------------------------------
// QKV projection via bf16 tensor cores, fused 2-term split, W-resident.
// Q stored fp32; K/V stored fp16 (halves gather L2 traffic).
// ---------------------------------------------------------------------------
extern __shared__ unsigned short smem_bf[];

__global__ __launch_bounds__(256, 2) void qkv_mma_kernel(
    const float* __restrict__ h,
    const float* __restrict__ Wq, const float* __restrict__ bq,
    const float* __restrict__ Wk, const float* __restrict__ bk,
    const float* __restrict__ Wv, const float* __restrict__ bv,
    int N, int ntiles)
{
    const float* W;
    const float* b;
    if (blockIdx.y == 0)      { W = Wq; b = bq; }
    else if (blockIdx.y == 1) { W = Wk; b = bk; }
    else                      { W = Wv; b = bv; }

    unsigned short* A_hi = smem_bf;                 // 64 x TS
    unsigned short* A_lo = A_hi + 64 * TS;          // 64 x TS
    unsigned short* B_hi = A_lo + 64 * TS;          // 128 x TS
    unsigned short* B_lo = B_hi + 128 * TS;         // 128 x TS

    const int tid  = threadIdx.x;
    const int warp = tid >> 5;
    const int lane = tid & 31;
    const int wm = warp & 3;           // m16 tile index
    const int wn = warp >> 2;          // n64 half
    const int m_base = wm * 16;
    const int n_base = wn * 64;

    // ---- Load + split W once per block ----
    #pragma unroll
    for (int i = 0; i < 16; i++) {
        int idx = tid + i * 256;
        int r   = idx >> 5;
        int c4  = idx & 31;
        float4 v = *(const float4*)&W[(size_t)r * HD + c4 * 4];
        float vv[4] = {v.x, v.y, v.z, v.w};
        unsigned short hs[4], ls[4];
        #pragma unroll
        for (int j = 0; j < 4; j++) {
            __nv_bfloat16 hb = __float2bfloat16(vv[j]);
            float lf = vv[j] - __bfloat162float(hb);
            __nv_bfloat16 lb = __float2bfloat16(lf);
            hs[j] = __bfloat16_as_ushort(hb);
            ls[j] = __bfloat16_as_ushort(lb);
        }
        uint2 ph, pl;
        ph.x = (unsigned)hs[0] | ((unsigned)hs[1] << 16);
        ph.y = (unsigned)hs[2] | ((unsigned)hs[3] << 16);
        pl.x = (unsigned)ls[0] | ((unsigned)ls[1] << 16);
        pl.y = (unsigned)ls[2] | ((unsigned)ls[3] << 16);
        *(uint2*)&B_hi[r * TS + c4 * 4] = ph;
        *(uint2*)&B_lo[r * TS + c4 * 4] = pl;
    }

    // Preload bias for this thread's 16 output columns
    const int t2 = (lane & 3) * 2;
    float2 bb[8];
    #pragma unroll
    for (int nt = 0; nt < 8; nt++) {
        int col = n_base + nt * 8 + t2;
        bb[nt].x = __ldg(&b[col]);
        bb[nt].y = __ldg(&b[col + 1]);
    }

    const int a_row  = m_base + (lane & 15);
    const int a_coff = (lane >> 4) * 8;
    const int b_roff = (lane & 7) + ((lane >> 3) & 1) * 8;
    const int b_col  = n_base + (lane >> 4) * 8;
    const int g      = lane >> 2;

    for (int tile = blockIdx.x; tile < ntiles; tile += gridDim.x) {
        const int row0 = tile * 64;

        __syncthreads();   // prior tile's MMAs done reading A smem

        // ---- Load h tile (64x128 fp32 = 2048 float4) -> split to bf16 hi/lo ----
        #pragma unroll
        for (int i = 0; i < 8; i++) {
            int idx = tid + i * 256;
            int r   = idx >> 5;
            int c4  = idx & 31;
            float4 v = make_float4(0.f, 0.f, 0.f, 0.f);
            int gr = row0 + r;
            if (gr < N) v = *(const float4*)&h[(size_t)gr * HD + c4 * 4];
            float vv[4] = {v.x, v.y, v.z, v.w};
            unsigned short hs[4], ls[4];
            #pragma unroll
            for (int j = 0; j < 4; j++) {
                __nv_bfloat16 hb = __float2bfloat16(vv[j]);
                float lf = vv[j] - __bfloat162float(hb);
                __nv_bfloat16 lb = __float2bfloat16(lf);
                hs[j] = __bfloat16_as_ushort(hb);
                ls[j] = __bfloat16_as_ushort(lb);
            }
            uint2 ph, pl;
            ph.x = (unsigned)hs[0] | ((unsigned)hs[1] << 16);
            ph.y = (unsigned)hs[2] | ((unsigned)hs[3] << 16);
            pl.x = (unsigned)ls[0] | ((unsigned)ls[1] << 16);
            pl.y = (unsigned)ls[2] | ((unsigned)ls[3] << 16);
            *(uint2*)&A_hi[r * TS + c4 * 4] = ph;
            *(uint2*)&A_lo[r * TS + c4 * 4] = pl;
        }
        __syncthreads();

        float acc[8][4];
        #pragma unroll
        for (int nt = 0; nt < 8; nt++)
            #pragma unroll
            for (int q = 0; q < 4; q++) acc[nt][q] = 0.f;

        #pragma unroll
        for (int ks = 0; ks < 8; ks++) {
            const int k0 = ks * 16;
            unsigned ah[4], al[4];
            {
                unsigned addr = (unsigned)__cvta_generic_to_shared(
                    &A_hi[a_row * TS + k0 + a_coff]);
                asm volatile(
                    "ldmatrix.sync.aligned.m8n8.x4.shared.b16 {%0,%1,%2,%3}, [%4];"
                    : "=r"(ah[0]), "=r"(ah[1]), "=r"(ah[2]), "=r"(ah[3]) : "r"(addr));
                addr = (unsigned)__cvta_generic_to_shared(
                    &A_lo[a_row * TS + k0 + a_coff]);
                asm volatile(
                    "ldmatrix.sync.aligned.m8n8.x4.shared.b16 {%0,%1,%2,%3}, [%4];"
                    : "=r"(al[0]), "=r"(al[1]), "=r"(al[2]), "=r"(al[3]) : "r"(addr));
            }
            unsigned bh[8][2], bl[8][2];
            #pragma unroll
            for (int np = 0; np < 4; np++) {
                unsigned addr = (unsigned)__cvta_generic_to_shared(
                    &B_hi[(k0 + b_roff) * TS + b_col + np * 16]);
                unsigned r0, r1, r2, r3;
                asm volatile(
                    "ldmatrix.sync.aligned.m8n8.x4.trans.shared.b16 {%0,%1,%2,%3}, [%4];"
                    : "=r"(r0), "=r"(r1), "=r"(r2), "=r"(r3) : "r"(addr));
                bh[np * 2][0] = r0; bh[np * 2][1] = r1;
                bh[np * 2 + 1][0] = r2; bh[np * 2 + 1][1] = r3;
                addr = (unsigned)__cvta_generic_to_shared(
                    &B_lo[(k0 + b_roff) * TS + b_col + np * 16]);
                asm volatile(
                    "ldmatrix.sync.aligned.m8n8.x4.trans.shared.b16 {%0,%1,%2,%3}, [%4];"
                    : "=r"(r0), "=r"(r1), "=r"(r2), "=r"(r3) : "r"(addr));
                bl[np * 2][0] = r0; bl[np * 2][1] = r1;
                bl[np * 2 + 1][0] = r2; bl[np * 2 + 1][1] = r3;
            }
            #pragma unroll
            for (int nt = 0; nt < 8; nt++) {
                asm volatile(
                    "mma.sync.aligned.m16n8k16.row.col.f32.bf16.bf16.f32 "
                    "{%0,%1,%2,%3}, {%4,%5,%6,%7}, {%8,%9}, {%0,%1,%2,%3};"
                    : "+f"(acc[nt][0]), "+f"(acc[nt][1]), "+f"(acc[nt][2]), "+f"(acc[nt][3])
                    : "r"(ah[0]), "r"(ah[1]), "r"(ah[2]), "r"(ah[3]),
                      "r"(bh[nt][0]), "r"(bh[nt][1]));
                asm volatile(
                    "mma.sync.aligned.m16n8k16.row.col.f32.bf16.bf16.f32 "
                    "{%0,%1,%2,%3}, {%4,%5,%6,%7}, {%8,%9}, {%0,%1,%2,%3};"
                    : "+f"(acc[nt][0]), "+f"(acc[nt][1]), "+f"(acc[nt][2]), "+f"(acc[nt][3])
                    : "r"(ah[0]), "r"(ah[1]), "r"(ah[2]), "r"(ah[3]),
                      "r"(bl[nt][0]), "r"(bl[nt][1]));
                asm volatile(
                    "mma.sync.aligned.m16n8k16.row.col.f32.bf16.bf16.f32 "
                    "{%0,%1,%2,%3}, {%4,%5,%6,%7}, {%8,%9}, {%0,%1,%2,%3};"
                    : "+f"(acc[nt][0]), "+f"(acc[nt][1]), "+f"(acc[nt][2]), "+f"(acc[nt][3])
                    : "r"(al[0]), "r"(al[1]), "r"(al[2]), "r"(al[3]),
                      "r"(bh[nt][0]), "r"(bh[nt][1]));
            }
        }

        // ---- Epilogue: Q -> fp32, K/V -> fp16 ----
        if (blockIdx.y == 0) {
            #pragma unroll
            for (int half = 0; half < 2; half++) {
                int r = row0 + m_base + g + half * 8;
                if (r < N) {
                    #pragma unroll
                    for (int nt = 0; nt < 8; nt++) {
                        int col = n_base + nt * 8 + t2;
                        float2 o;
                        o.x = acc[nt][half * 2 + 0] + bb[nt].x;
                        o.y = acc[nt][half * 2 + 1] + bb[nt].y;
                        *(float2*)&g_Q[(size_t)r * HD + col] = o;
                    }
                }
            }
        } else {
            __half* outh = (blockIdx.y == 1) ? g_Kh : g_Vh;
            #pragma unroll
            for (int half = 0; half < 2; half++) {
                int r = row0 + m_base + g + half * 8;
                if (r < N) {
                    #pragma unroll
                    for (int nt = 0; nt < 8; nt++) {
                        int col = n_base + nt * 8 + t2;
                        float ox = acc[nt][half * 2 + 0] + bb[nt].x;
                        float oy = acc[nt][half * 2 + 1] + bb[nt].y;
                        *(__half2*)&outh[(size_t)r * HD + col] =
                            __floats2half2_rn(ox, oy);
                    }
                }
            }
        }
    }
}

// ---------------------------------------------------------------------------
// CSR build: hist -> warp-aggregated start assignment -> scatter.
// ---------------------------------------------------------------------------
__global__ __launch_bounds__(256) void hist_kernel(const int* __restrict__ dst, int E)
{
    int e = blockIdx.x * blockDim.x + threadIdx.x;
    if (e < E) atomicAdd(&g_count[dst[e]], 1);
}

__global__ __launch_bounds__(256) void assign_starts_kernel(int N)
{
    int i = blockIdx.x * blockDim.x + threadIdx.x;
    int lane = threadIdx.x & 31;
    int c = (i < N) ? g_count[i] : 0;

    int p = c;
    #pragma unroll
    for (int off = 1; off < 32; off <<= 1) {
        int t = __shfl_up_sync(0xffffffffu, p, off);
        if (lane >= off) p += t;
    }
    int warp_total = __shfl_sync(0xffffffffu, p, 31);
    int base = 0;
    if (lane == 0) base = atomicAdd(&g_total[0], warp_total);
    base = __shfl_sync(0xffffffffu, base, 0);

    if (i < N) {
        int s = base + p - c;
        g_start[i]  = s;
        g_cursor[i] = s;
    }
}

__global__ __launch_bounds__(256) void scatter_kernel(
    const int* __restrict__ src, const int* __restrict__ dst, int E)
{
    int e = blockIdx.x * blockDim.x + threadIdx.x;
    if (e < E) {
        int pos = atomicAdd(&g_cursor[dst[e]], 1);
        g_csr_src[pos] = src[e];
    }
}

// ---------------------------------------------------------------------------
// Gather: one warp per dst node. K/V are fp16 (8B per lane = 4 channels).
// ---------------------------------------------------------------------------
__global__ __launch_bounds__(256) void gather_kernel(
    const float* __restrict__ dis,
    const float* __restrict__ att_w, const float* __restrict__ att_b,
    float* __restrict__ out, int N)
{
    int d = (blockIdx.x * blockDim.x + threadIdx.x) >> 5;
    int lane = threadIdx.x & 31;
    if (d >= N) return;

    int start = g_start[d];
    int cnt   = g_count[d];
    int head  = lane >> 2;

    float4 Q4 = *(const float4*)&g_Q[(size_t)d * HD + lane * 4];
    float bias = __ldg(&dis[d]) * __ldg(&att_w[head]) + __ldg(&att_b[head]);

    float4 acc = make_float4(0.f, 0.f, 0.f, 0.f);
    float z = 0.f;

    for (int base = 0; base < cnt; base += 32) {
        int m = min(32, cnt - base);
        int s_l = (base + lane < cnt) ? g_csr_src[start + base + lane] : 0;

        int s0 = __shfl_sync(0xffffffffu, s_l, 0);
        uint2 Kr = *(const uint2*)&g_Kh[(size_t)s0 * HD + lane * 4];
        uint2 Vr = *(const uint2*)&g_Vh[(size_t)s0 * HD + lane * 4];

        for (int i = 0; i < m; i++) {
            uint2 Kc = Kr, Vc = Vr;
            if (i + 1 < m) {
                int sn = __shfl_sync(0xffffffffu, s_l, i + 1);
                Kr = *(const uint2*)&g_Kh[(size_t)sn * HD + lane * 4];
                Vr = *(const uint2*)&g_Vh[(size_t)sn * HD + lane * 4];
            }
            float2 k01 = __half22float2(*(const __half2*)&Kc.x);
            float2 k23 = __half22float2(*(const __half2*)&Kc.y);
            float dot = k01.x * Q4.x + k01.y * Q4.y + k23.x * Q4.z + k23.y * Q4.w;
            dot += __shfl_xor_sync(0xffffffffu, dot, 1);
            dot += __shfl_xor_sync(0xffffffffu, dot, 2);
            float sc = (dot + bias) * 0.25f;
            sc = fminf(fmaxf(sc, -5.f), 5.f);
            float w = expf(sc);
            float2 v01 = __half22float2(*(const __half2*)&Vc.x);
            float2 v23 = __half22float2(*(const __half2*)&Vc.y);
            acc.x += v01.x * w;
            acc.y += v01.y * w;
            acc.z += v23.x * w;
            acc.w += v23.y * w;
            z += w;
        }
    }

    float inv = 1.0f / z;
    float4 o = make_float4(acc.x * inv, acc.y * inv, acc.z * inv, acc.w * inv);
    *(float4*)&out[(size_t)d * HD + lane * 4] = o;
}

// ---------------------------------------------------------------------------
extern "C" void kernel_launch(void* const* d_in, const int* in_sizes, int n_in,
                              void* d_out, int out_size)
{
    const float* h     = (const float*)d_in[0];
    const float* dis   = (const float*)d_in[1];
    const float* Wq    = (const float*)d_in[2];
    const float* bq    = (const float*)d_in[3];
    const float* Wk    = (const float*)d_in[4];
    const float* bk    = (const float*)d_in[5];
    const float* Wv    = (const float*)d_in[6];
    const float* bv    = (const float*)d_in[7];
    const float* att_w = (const float*)d_in[8];
    const float* att_b = (const float*)d_in[9];
    const int*   src   = (const int*)d_in[10];
    const int*   dst   = (const int*)d_in[11];

    int N = in_sizes[1];
    int E = in_sizes[10];
    float* out = (float*)d_out;

    static cudaStream_t s2 = nullptr;
    static cudaEvent_t ev_fork = nullptr, ev_join = nullptr;
    static bool inited = false;
    if (!inited) {
        cudaStreamCreateWithFlags(&s2, cudaStreamNonBlocking);
        cudaEventCreateWithFlags(&ev_fork, cudaEventDisableTiming);
        cudaEventCreateWithFlags(&ev_join, cudaEventDisableTiming);
        size_t sb = (size_t)(64 + 64 + 128 + 128) * TS * sizeof(unsigned short);
        cudaFuncSetAttribute(qkv_mma_kernel,
                             cudaFuncAttributeMaxDynamicSharedMemorySize, (int)sb);
        inited = true;
    }
    size_t smem_bytes = (size_t)(64 + 64 + 128 + 128) * TS * sizeof(unsigned short);

    // ---- Fork: CSR build on s2 concurrently with QKV on main stream ----
    cudaEventRecord(ev_fork, 0);
    cudaStreamWaitEvent(s2, ev_fork, 0);

    void* cptr = nullptr;
    cudaGetSymbolAddress(&cptr, g_count);
    cudaMemsetAsync(cptr, 0, (size_t)N * sizeof(int), s2);
    void* tptr = nullptr;
    cudaGetSymbolAddress(&tptr, g_total);
    cudaMemsetAsync(tptr, 0, sizeof(int), s2);
    hist_kernel<<<(E + 255) / 256, 256, 0, s2>>>(dst, E);
    assign_starts_kernel<<<(N + 255) / 256, 256, 0, s2>>>(N);
    scatter_kernel<<<(E + 255) / 256, 256, 0, s2>>>(src, dst, E);
    cudaEventRecord(ev_join, s2);

    int ntiles = (N + 63) / 64;
    dim3 qkv_grid(98, 3);
    qkv_mma_kernel<<<qkv_grid, 256, smem_bytes>>>(h, Wq, bq, Wk, bk, Wv, bv, N, ntiles);

    cudaStreamWaitEvent(0, ev_join, 0);
    gather_kernel<<<((size_t)N * 32 + 255) / 256, 256>>>(dis, att_w, att_b, out, N);
}

// round 8
// speedup vs baseline: 2.6262x; 1.0626x over previous
#include <cuda_runtime.h>
#include <cuda_bf16.h>
#include <cuda_fp16.h>
#include <math.h>

#define MAXN 50000
#define MAXE 800000
#define HD 128
#define NHEAD 8
#define TS 136   // smem tile stride in bf16 elements (272B rows: conflict-free ldmatrix)

__device__ float  g_Q[(size_t)MAXN * HD];
__device__ __half g_Kh[(size_t)MAXN * HD];
__device__ __half g_Vh[(size_t)MAXN * HD];
__device__ int    g_count[MAXN];
__device__ int    g_start[MAXN];
__device__ int    g_cursor[MAXN];
__device__ int    g_csr_src[MAXE];
__device__ int    g_total[1];

// ---------------------------------------------------------------------------
// QKV projection via bf16 tensor cores, fused 2-term split, W-resident.
// Q stored fp32; K/V stored fp16.
// ---------------------------------------------------------------------------
extern __shared__ unsigned short smem_bf[];

__global__ __launch_bounds__(256, 2) void qkv_mma_kernel(
    const float* __restrict__ h,
    const float* __restrict__ Wq, const float* __restrict__ bq,
    const float* __restrict__ Wk, const float* __restrict__ bk,
    const float* __restrict__ Wv, const float* __restrict__ bv,
    int N, int ntiles)
{
    const float* W;
    const float* b;
    if (blockIdx.y == 0)      { W = Wq; b = bq; }
    else if (blockIdx.y == 1) { W = Wk; b = bk; }
    else                      { W = Wv; b = bv; }

    unsigned short* A_hi = smem_bf;                 // 64 x TS
    unsigned short* A_lo = A_hi + 64 * TS;          // 64 x TS
    unsigned short* B_hi = A_lo + 64 * TS;          // 128 x TS
    unsigned short* B_lo = B_hi + 128 * TS;         // 128 x TS

    const int tid  = threadIdx.x;
    const int warp = tid >> 5;
    const int lane = tid & 31;
    const int wm = warp & 3;
    const int wn = warp >> 2;
    const int m_base = wm * 16;
    const int n_base = wn * 64;

    // ---- Load + split W once per block ----
    #pragma unroll
    for (int i = 0; i < 16; i++) {
        int idx = tid + i * 256;
        int r   = idx >> 5;
        int c4  = idx & 31;
        float4 v = *(const float4*)&W[(size_t)r * HD + c4 * 4];
        float vv[4] = {v.x, v.y, v.z, v.w};
        unsigned short hs[4], ls[4];
        #pragma unroll
        for (int j = 0; j < 4; j++) {
            __nv_bfloat16 hb = __float2bfloat16(vv[j]);
            float lf = vv[j] - __bfloat162float(hb);
            __nv_bfloat16 lb = __float2bfloat16(lf);
            hs[j] = __bfloat16_as_ushort(hb);
            ls[j] = __bfloat16_as_ushort(lb);
        }
        uint2 ph, pl;
        ph.x = (unsigned)hs[0] | ((unsigned)hs[1] << 16);
        ph.y = (unsigned)hs[2] | ((unsigned)hs[3] << 16);
        pl.x = (unsigned)ls[0] | ((unsigned)ls[1] << 16);
        pl.y = (unsigned)ls[2] | ((unsigned)ls[3] << 16);
        *(uint2*)&B_hi[r * TS + c4 * 4] = ph;
        *(uint2*)&B_lo[r * TS + c4 * 4] = pl;
    }

    const int t2 = (lane & 3) * 2;
    float2 bb[8];
    #pragma unroll
    for (int nt = 0; nt < 8; nt++) {
        int col = n_base + nt * 8 + t2;
        bb[nt].x = __ldg(&b[col]);
        bb[nt].y = __ldg(&b[col + 1]);
    }

    const int a_row  = m_base + (lane & 15);
    const int a_coff = (lane >> 4) * 8;
    const int b_roff = (lane & 7) + ((lane >> 3) & 1) * 8;
    const int b_col  = n_base + (lane >> 4) * 8;
    const int g      = lane >> 2;

    for (int tile = blockIdx.x; tile < ntiles; tile += gridDim.x) {
        const int row0 = tile * 64;

        __syncthreads();

        // ---- Load h tile -> split to bf16 hi/lo ----
        #pragma unroll
        for (int i = 0; i < 8; i++) {
            int idx = tid + i * 256;
            int r   = idx >> 5;
            int c4  = idx & 31;
            float4 v = make_float4(0.f, 0.f, 0.f, 0.f);
            int gr = row0 + r;
            if (gr < N) v = *(const float4*)&h[(size_t)gr * HD + c4 * 4];
            float vv[4] = {v.x, v.y, v.z, v.w};
            unsigned short hs[4], ls[4];
            #pragma unroll
            for (int j = 0; j < 4; j++) {
                __nv_bfloat16 hb = __float2bfloat16(vv[j]);
                float lf = vv[j] - __bfloat162float(hb);
                __nv_bfloat16 lb = __float2bfloat16(lf);
                hs[j] = __bfloat16_as_ushort(hb);
                ls[j] = __bfloat16_as_ushort(lb);
            }
            uint2 ph, pl;
            ph.x = (unsigned)hs[0] | ((unsigned)hs[1] << 16);
            ph.y = (unsigned)hs[2] | ((unsigned)hs[3] << 16);
            pl.x = (unsigned)ls[0] | ((unsigned)ls[1] << 16);
            pl.y = (unsigned)ls[2] | ((unsigned)ls[3] << 16);
            *(uint2*)&A_hi[r * TS + c4 * 4] = ph;
            *(uint2*)&A_lo[r * TS + c4 * 4] = pl;
        }
        __syncthreads();

        float acc[8][4];
        #pragma unroll
        for (int nt = 0; nt < 8; nt++)
            #pragma unroll
            for (int q = 0; q < 4; q++) acc[nt][q] = 0.f;

        #pragma unroll
        for (int ks = 0; ks < 8; ks++) {
            const int k0 = ks * 16;
            unsigned ah[4], al[4];
            {
                unsigned addr = (unsigned)__cvta_generic_to_shared(
                    &A_hi[a_row * TS + k0 + a_coff]);
                asm volatile(
                    "ldmatrix.sync.aligned.m8n8.x4.shared.b16 {%0,%1,%2,%3}, [%4];"
                    : "=r"(ah[0]), "=r"(ah[1]), "=r"(ah[2]), "=r"(ah[3]) : "r"(addr));
                addr = (unsigned)__cvta_generic_to_shared(
                    &A_lo[a_row * TS + k0 + a_coff]);
                asm volatile(
                    "ldmatrix.sync.aligned.m8n8.x4.shared.b16 {%0,%1,%2,%3}, [%4];"
                    : "=r"(al[0]), "=r"(al[1]), "=r"(al[2]), "=r"(al[3]) : "r"(addr));
            }
            unsigned bh[8][2], bl[8][2];
            #pragma unroll
            for (int np = 0; np < 4; np++) {
                unsigned addr = (unsigned)__cvta_generic_to_shared(
                    &B_hi[(k0 + b_roff) * TS + b_col + np * 16]);
                unsigned r0, r1, r2, r3;
                asm volatile(
                    "ldmatrix.sync.aligned.m8n8.x4.trans.shared.b16 {%0,%1,%2,%3}, [%4];"
                    : "=r"(r0), "=r"(r1), "=r"(r2), "=r"(r3) : "r"(addr));
                bh[np * 2][0] = r0; bh[np * 2][1] = r1;
                bh[np * 2 + 1][0] = r2; bh[np * 2 + 1][1] = r3;
                addr = (unsigned)__cvta_generic_to_shared(
                    &B_lo[(k0 + b_roff) * TS + b_col + np * 16]);
                asm volatile(
                    "ldmatrix.sync.aligned.m8n8.x4.trans.shared.b16 {%0,%1,%2,%3}, [%4];"
                    : "=r"(r0), "=r"(r1), "=r"(r2), "=r"(r3) : "r"(addr));
                bl[np * 2][0] = r0; bl[np * 2][1] = r1;
                bl[np * 2 + 1][0] = r2; bl[np * 2 + 1][1] = r3;
            }
            #pragma unroll
            for (int nt = 0; nt < 8; nt++) {
                asm volatile(
                    "mma.sync.aligned.m16n8k16.row.col.f32.bf16.bf16.f32 "
                    "{%0,%1,%2,%3}, {%4,%5,%6,%7}, {%8,%9}, {%0,%1,%2,%3};"
                    : "+f"(acc[nt][0]), "+f"(acc[nt][1]), "+f"(acc[nt][2]), "+f"(acc[nt][3])
                    : "r"(ah[0]), "r"(ah[1]), "r"(ah[2]), "r"(ah[3]),
                      "r"(bh[nt][0]), "r"(bh[nt][1]));
                asm volatile(
                    "mma.sync.aligned.m16n8k16.row.col.f32.bf16.bf16.f32 "
                    "{%0,%1,%2,%3}, {%4,%5,%6,%7}, {%8,%9}, {%0,%1,%2,%3};"
                    : "+f"(acc[nt][0]), "+f"(acc[nt][1]), "+f"(acc[nt][2]), "+f"(acc[nt][3])
                    : "r"(ah[0]), "r"(ah[1]), "r"(ah[2]), "r"(ah[3]),
                      "r"(bl[nt][0]), "r"(bl[nt][1]));
                asm volatile(
                    "mma.sync.aligned.m16n8k16.row.col.f32.bf16.bf16.f32 "
                    "{%0,%1,%2,%3}, {%4,%5,%6,%7}, {%8,%9}, {%0,%1,%2,%3};"
                    : "+f"(acc[nt][0]), "+f"(acc[nt][1]), "+f"(acc[nt][2]), "+f"(acc[nt][3])
                    : "r"(al[0]), "r"(al[1]), "r"(al[2]), "r"(al[3]),
                      "r"(bh[nt][0]), "r"(bh[nt][1]));
            }
        }

        // ---- Epilogue: Q -> fp32, K/V -> fp16 ----
        if (blockIdx.y == 0) {
            #pragma unroll
            for (int half = 0; half < 2; half++) {
                int r = row0 + m_base + g + half * 8;
                if (r < N) {
                    #pragma unroll
                    for (int nt = 0; nt < 8; nt++) {
                        int col = n_base + nt * 8 + t2;
                        float2 o;
                        o.x = acc[nt][half * 2 + 0] + bb[nt].x;
                        o.y = acc[nt][half * 2 + 1] + bb[nt].y;
                        *(float2*)&g_Q[(size_t)r * HD + col] = o;
                    }
                }
            }
        } else {
            __half* outh = (blockIdx.y == 1) ? g_Kh : g_Vh;
            #pragma unroll
            for (int half = 0; half < 2; half++) {
                int r = row0 + m_base + g + half * 8;
                if (r < N) {
                    #pragma unroll
                    for (int nt = 0; nt < 8; nt++) {
                        int col = n_base + nt * 8 + t2;
                        float ox = acc[nt][half * 2 + 0] + bb[nt].x;
                        float oy = acc[nt][half * 2 + 1] + bb[nt].y;
                        *(__half2*)&outh[(size_t)r * HD + col] =
                            __floats2half2_rn(ox, oy);
                    }
                }
            }
        }
    }
}

// ---------------------------------------------------------------------------
// CSR build
// ---------------------------------------------------------------------------
__global__ __launch_bounds__(256) void hist_kernel(const int* __restrict__ dst, int E)
{
    int e = blockIdx.x * blockDim.x + threadIdx.x;
    if (e < E) atomicAdd(&g_count[dst[e]], 1);
}

__global__ __launch_bounds__(256) void assign_starts_kernel(int N)
{
    int i = blockIdx.x * blockDim.x + threadIdx.x;
    int lane = threadIdx.x & 31;
    int c = (i < N) ? g_count[i] : 0;

    int p = c;
    #pragma unroll
    for (int off = 1; off < 32; off <<= 1) {
        int t = __shfl_up_sync(0xffffffffu, p, off);
        if (lane >= off) p += t;
    }
    int warp_total = __shfl_sync(0xffffffffu, p, 31);
    int base = 0;
    if (lane == 0) base = atomicAdd(&g_total[0], warp_total);
    base = __shfl_sync(0xffffffffu, base, 0);

    if (i < N) {
        int s = base + p - c;
        g_start[i]  = s;
        g_cursor[i] = s;
    }
}

__global__ __launch_bounds__(256) void scatter_kernel(
    const int* __restrict__ src, const int* __restrict__ dst, int E)
{
    int e = blockIdx.x * blockDim.x + threadIdx.x;
    if (e < E) {
        int pos = atomicAdd(&g_cursor[dst[e]], 1);
        g_csr_src[pos] = src[e];
    }
}

// ---------------------------------------------------------------------------
// Gather v2: one warp per dst node, TWO edges per iteration.
// lane = half*16 + sub; half in {0,1} handles even/odd edges.
// Each lane covers 8 fp16 channels (uint4 = 16B); head = sub>>1.
// Dot: 8-wide in-lane + one shfl_xor(1). Final cross-half shfl_xor(16).
// ---------------------------------------------------------------------------
__global__ __launch_bounds__(256) void gather_kernel(
    const float* __restrict__ dis,
    const float* __restrict__ att_w, const float* __restrict__ att_b,
    float* __restrict__ out, int N)
{
    int d = (blockIdx.x * blockDim.x + threadIdx.x) >> 5;
    int lane = threadIdx.x & 31;
    if (d >= N) return;

    const int half = lane >> 4;      // 0: even edges, 1: odd edges
    const int sub  = lane & 15;      // channel group 0..15
    const int head = sub >> 1;       // 0..7
    const int c0   = sub * 8;        // first of 8 channels

    float4 q0 = *(const float4*)&g_Q[(size_t)d * HD + c0];
    float4 q1 = *(const float4*)&g_Q[(size_t)d * HD + c0 + 4];
    float bias = __ldg(&dis[d]) * __ldg(&att_w[head]) + __ldg(&att_b[head]);

    float a0 = 0.f, a1 = 0.f, a2 = 0.f, a3 = 0.f;
    float a4 = 0.f, a5 = 0.f, a6 = 0.f, a7 = 0.f;
    float z = 0.f;

    int start = g_start[d];
    int cnt   = g_count[d];

    for (int base = 0; base < cnt; base += 32) {
        int m = min(32, cnt - base);
        int s_l = (base + lane < cnt) ? g_csr_src[start + base + lane] : 0;
        int iters = (m + 1) >> 1;

        int e0 = half;
        int sn = __shfl_sync(0xffffffffu, s_l, e0);
        bool vnext = (e0 < m);
        uint4 Kr = *(const uint4*)&g_Kh[(size_t)sn * HD + c0];
        uint4 Vr = *(const uint4*)&g_Vh[(size_t)sn * HD + c0];

        for (int i = 0; i < iters; i++) {
            uint4 Kc = Kr, Vc = Vr;
            bool v = vnext;
            if (i + 1 < iters) {
                int en = 2 * (i + 1) + half;
                int s2 = __shfl_sync(0xffffffffu, s_l, en);
                vnext = (en < m);
                Kr = *(const uint4*)&g_Kh[(size_t)s2 * HD + c0];
                Vr = *(const uint4*)&g_Vh[(size_t)s2 * HD + c0];
            }
            float2 k0 = __half22float2(*(const __half2*)&Kc.x);
            float2 k1 = __half22float2(*(const __half2*)&Kc.y);
            float2 k2 = __half22float2(*(const __half2*)&Kc.z);
            float2 k3 = __half22float2(*(const __half2*)&Kc.w);
            float dot = k0.x * q0.x + k0.y * q0.y + k1.x * q0.z + k1.y * q0.w
                      + k2.x * q1.x + k2.y * q1.y + k3.x * q1.z + k3.y * q1.w;
            dot += __shfl_xor_sync(0xffffffffu, dot, 1);
            float sc = (dot + bias) * 0.25f;
            sc = fminf(fmaxf(sc, -5.f), 5.f);
            float w = v ? __expf(sc) : 0.f;

            float2 v0 = __half22float2(*(const __half2*)&Vc.x);
            float2 v1 = __half22float2(*(const __half2*)&Vc.y);
            float2 v2 = __half22float2(*(const __half2*)&Vc.z);
            float2 v3 = __half22float2(*(const __half2*)&Vc.w);
            a0 += v0.x * w;  a1 += v0.y * w;
            a2 += v1.x * w;  a3 += v1.y * w;
            a4 += v2.x * w;  a5 += v2.y * w;
            a6 += v3.x * w;  a7 += v3.y * w;
            z += w;
        }
    }

    // Combine even/odd halves (lane l <-> l^16 cover the same channels)
    a0 += __shfl_xor_sync(0xffffffffu, a0, 16);
    a1 += __shfl_xor_sync(0xffffffffu, a1, 16);
    a2 += __shfl_xor_sync(0xffffffffu, a2, 16);
    a3 += __shfl_xor_sync(0xffffffffu, a3, 16);
    a4 += __shfl_xor_sync(0xffffffffu, a4, 16);
    a5 += __shfl_xor_sync(0xffffffffu, a5, 16);
    a6 += __shfl_xor_sync(0xffffffffu, a6, 16);
    a7 += __shfl_xor_sync(0xffffffffu, a7, 16);
    z  += __shfl_xor_sync(0xffffffffu, z, 16);

    if (half == 0) {
        float inv = 1.0f / z;
        float4 o0 = make_float4(a0 * inv, a1 * inv, a2 * inv, a3 * inv);
        float4 o1 = make_float4(a4 * inv, a5 * inv, a6 * inv, a7 * inv);
        *(float4*)&out[(size_t)d * HD + c0]     = o0;
        *(float4*)&out[(size_t)d * HD + c0 + 4] = o1;
    }
}

// ---------------------------------------------------------------------------
extern "C" void kernel_launch(void* const* d_in, const int* in_sizes, int n_in,
                              void* d_out, int out_size)
{
    const float* h     = (const float*)d_in[0];
    const float* dis   = (const float*)d_in[1];
    const float* Wq    = (const float*)d_in[2];
    const float* bq    = (const float*)d_in[3];
    const float* Wk    = (const float*)d_in[4];
    const float* bk    = (const float*)d_in[5];
    const float* Wv    = (const float*)d_in[6];
    const float* bv    = (const float*)d_in[7];
    const float* att_w = (const float*)d_in[8];
    const float* att_b = (const float*)d_in[9];
    const int*   src   = (const int*)d_in[10];
    const int*   dst   = (const int*)d_in[11];

    int N = in_sizes[1];
    int E = in_sizes[10];
    float* out = (float*)d_out;

    static cudaStream_t s2 = nullptr;
    static cudaEvent_t ev_fork = nullptr, ev_join = nullptr;
    static bool inited = false;
    if (!inited) {
        cudaStreamCreateWithFlags(&s2, cudaStreamNonBlocking);
        cudaEventCreateWithFlags(&ev_fork, cudaEventDisableTiming);
        cudaEventCreateWithFlags(&ev_join, cudaEventDisableTiming);
        size_t sb = (size_t)(64 + 64 + 128 + 128) * TS * sizeof(unsigned short);
        cudaFuncSetAttribute(qkv_mma_kernel,
                             cudaFuncAttributeMaxDynamicSharedMemorySize, (int)sb);
        inited = true;
    }
    size_t smem_bytes = (size_t)(64 + 64 + 128 + 128) * TS * sizeof(unsigned short);

    // ---- Fork: CSR build on s2 concurrently with QKV on main stream ----
    cudaEventRecord(ev_fork, 0);
    cudaStreamWaitEvent(s2, ev_fork, 0);

    void* cptr = nullptr;
    cudaGetSymbolAddress(&cptr, g_count);
    cudaMemsetAsync(cptr, 0, (size_t)N * sizeof(int), s2);
    void* tptr = nullptr;
    cudaGetSymbolAddress(&tptr, g_total);
    cudaMemsetAsync(tptr, 0, sizeof(int), s2);
    hist_kernel<<<(E + 255) / 256, 256, 0, s2>>>(dst, E);
    assign_starts_kernel<<<(N + 255) / 256, 256, 0, s2>>>(N);
    scatter_kernel<<<(E + 255) / 256, 256, 0, s2>>>(src, dst, E);
    cudaEventRecord(ev_join, s2);

    int ntiles = (N + 63) / 64;
    dim3 qkv_grid(98, 3);
    qkv_mma_kernel<<<qkv_grid, 256, smem_bytes>>>(h, Wq, bq, Wk, bk, Wv, bv, N, ntiles);

    cudaStreamWaitEvent(0, ev_join, 0);
    gather_kernel<<<((size_t)N * 32 + 255) / 256, 256>>>(dis, att_w, att_b, out, N);
}